// round 1
// baseline (speedup 1.0000x reference)
#include <cuda_runtime.h>
#include <math.h>

#define T_SEQ   1024
#define DMODEL  1024
#define NHEAD   16
#define HTOT    64
#define DH      64
#define QKV_N   (HTOT*DH)   /* 4096 */
#define ATTN_SCALE 0.125f
#define SIGM_SCALE 1.8137993642342178f   /* pi/sqrt(3) */

// ---------------- scratch (device globals; no allocation allowed) -------------
__device__ float  g_Q[T_SEQ*QKV_N];        // (t, 4096)
__device__ float  g_K[T_SEQ*DMODEL];       // (t, 1024)
__device__ float  g_V[T_SEQ*QKV_N];        // (t, 4096)
__device__ float  g_kscale[NHEAD*T_SEQ];   // ATTN_SCALE / sqrt(clip(|k|^2,1e-6))
__device__ float2 g_rope[T_SEQ*32];        // (t, pair) -> (cos, sin)
__device__ float  g_ctx[T_SEQ*QKV_N];      // per-head context, (t, 4096)
__device__ float  g_ctxavg[T_SEQ*DMODEL];  // branch-averaged context

// ---------------- SGEMM: C = A(MxK) @ B(KxN) + bias, M=1024 ------------------
// 128x128 tile, BK=16, 256 threads, 8x8 per thread.
__global__ __launch_bounds__(256, 2)
void sgemm_bias(const float* __restrict__ A, const float* __restrict__ B,
                const float* __restrict__ bias, float* __restrict__ C,
                int N, int K)
{
    __shared__ float As[16][132];   // transposed A tile, padded (2-way store max)
    __shared__ float Bs[16][128];

    const int tid = threadIdx.x;
    const int tx  = tid & 15;
    const int ty  = tid >> 4;
    const int rowBase = blockIdx.y * 128;
    const int colBase = blockIdx.x * 128;

    float acc[8][8] = {};

    for (int k0 = 0; k0 < K; k0 += 16) {
        #pragma unroll
        for (int r = 0; r < 2; r++) {
            int idx  = tid + r * 256;              // 0..511
            // A: 128x16 -> transposed store
            int arow = idx >> 2;
            int ac   = (idx & 3) << 2;
            float4 va = *(const float4*)(A + (rowBase + arow) * K + k0 + ac);
            As[ac + 0][arow] = va.x;
            As[ac + 1][arow] = va.y;
            As[ac + 2][arow] = va.z;
            As[ac + 3][arow] = va.w;
            // B: 16x128 row-major
            int brow = idx >> 5;
            int bc   = (idx & 31) << 2;
            *(float4*)&Bs[brow][bc] =
                *(const float4*)(B + (k0 + brow) * N + colBase + bc);
        }
        __syncthreads();

        #pragma unroll
        for (int k = 0; k < 16; k++) {
            float a[8], b[8];
            *(float4*)&a[0] = *(float4*)&As[k][ty * 8];
            *(float4*)&a[4] = *(float4*)&As[k][ty * 8 + 4];
            *(float4*)&b[0] = *(float4*)&Bs[k][tx * 8];
            *(float4*)&b[4] = *(float4*)&Bs[k][tx * 8 + 4];
            #pragma unroll
            for (int i = 0; i < 8; i++)
                #pragma unroll
                for (int j = 0; j < 8; j++)
                    acc[i][j] = fmaf(a[i], b[j], acc[i][j]);
        }
        __syncthreads();
    }

    #pragma unroll
    for (int i = 0; i < 8; i++) {
        int m = rowBase + ty * 8 + i;
        #pragma unroll
        for (int j = 0; j < 8; j += 4) {
            int n = colBase + tx * 8 + j;
            float4 o;
            o.x = acc[i][j + 0] + bias[n + 0];
            o.y = acc[i][j + 1] + bias[n + 1];
            o.z = acc[i][j + 2] + bias[n + 2];
            o.w = acc[i][j + 3] + bias[n + 3];
            *(float4*)(C + m * N + n) = o;
        }
    }
}

// ---------------- RoPE cos/sin table ------------------------------------------
__global__ void rope_table_kernel()
{
    int idx = blockIdx.x * blockDim.x + threadIdx.x;   // t*32 + pair
    if (idx >= T_SEQ * 32) return;
    int t = idx >> 5;
    int p = idx & 31;
    // inv_freq = 10000^(-p/32) = exp(-p * ln(10000)/32)
    float inv = expf(-(float)p * 0.28782313662425575f);
    float ang = (float)t * inv;
    float s, c;
    sincosf(ang, &s, &c);
    g_rope[idx] = make_float2(c, s);
}

// ---------------- key norm scale (rope preserves |k|^2 -> use pre-rope K) -----
__global__ void kscale_kernel()
{
    int gw   = (blockIdx.x * blockDim.x + threadIdx.x) >> 5;  // warp per (hb,t)
    int lane = threadIdx.x & 31;
    if (gw >= NHEAD * T_SEQ) return;
    int hb = gw >> 10;
    int t  = gw & 1023;
    const float* kp = g_K + t * DMODEL + hb * DH;
    float2 v = *(const float2*)(kp + 2 * lane);
    float s = v.x * v.x + v.y * v.y;
    #pragma unroll
    for (int o = 16; o; o >>= 1) s += __shfl_xor_sync(0xffffffffu, s, o);
    if (lane == 0)
        g_kscale[hb * T_SEQ + t] = ATTN_SCALE / sqrtf(fmaxf(s, 1e-6f));
}

// ---------------- attention: one block = (32 queries, 1 head) -----------------
// Tiles: Q 32x64 (roped on load), loop over 64-key tiles (K roped on load).
// Thread map: 16x16 threads; rows i = ty + 16*ii (ii<2), cols j = tx + 16*jj (jj<4).
__global__ __launch_bounds__(256)
void attn_kernel(const float* __restrict__ sink_sc,
                 const float* __restrict__ v_nulls)
{
    __shared__ float Qs[32][68];     // roped Q, padded: conflict-free a-loads
    __shared__ float KWs[64][65];    // roped K tile; reused as W tile
    __shared__ float Vs[64][68];     // V tile

    const int qi  = blockIdx.x;      // 0..31 query tiles
    const int h   = blockIdx.y;      // 0..63 heads
    const int hb  = h & 15;          // shared K head
    const int tid = threadIdx.x;
    const int tx  = tid & 15;
    const int ty  = tid >> 4;
    const int t0  = qi * 32;

    // ---- load + rope Q tile (32x64): 512 float4, 2 per thread ----
    #pragma unroll
    for (int r = 0; r < 2; r++) {
        int idx = tid + r * 256;
        int i   = idx >> 4;
        int d4  = idx & 15;
        int t   = t0 + i;
        float4 v   = *(const float4*)(g_Q + t * QKV_N + h * DH + d4 * 4);
        float2 cs0 = g_rope[t * 32 + 2 * d4];
        float2 cs1 = g_rope[t * 32 + 2 * d4 + 1];
        Qs[i][2 * d4]      = v.x * cs0.x - v.y * cs0.y;
        Qs[i][2 * d4 + 1]  = v.z * cs1.x - v.w * cs1.y;
        Qs[i][2 * d4 + 32] = v.x * cs0.y + v.y * cs0.x;
        Qs[i][2 * d4 + 33] = v.z * cs1.y + v.w * cs1.x;
    }

    float acc[2][4] = {};
    float rowsum[2] = {};
    const int nkt = (qi >> 1) + 1;   // 64-key tiles covering s <= t0+31

    for (int kt = 0; kt < nkt; kt++) {
        const int s0 = kt * 64;
        __syncthreads();  // protect prev-iter KWs/Vs reads (and Qs writes, iter 0)

        // ---- load + rope K tile, load V tile: 64x64 each, 4 f4 per thread ----
        #pragma unroll
        for (int r = 0; r < 4; r++) {
            int idx = tid + r * 256;
            int j   = idx >> 4;
            int d4  = idx & 15;
            int s   = s0 + j;
            float4 kv  = *(const float4*)(g_K + s * DMODEL + hb * DH + d4 * 4);
            float2 cs0 = g_rope[s * 32 + 2 * d4];
            float2 cs1 = g_rope[s * 32 + 2 * d4 + 1];
            KWs[j][2 * d4]      = kv.x * cs0.x - kv.y * cs0.y;
            KWs[j][2 * d4 + 1]  = kv.z * cs1.x - kv.w * cs1.y;
            KWs[j][2 * d4 + 32] = kv.x * cs0.y + kv.y * cs0.x;
            KWs[j][2 * d4 + 33] = kv.z * cs1.y + kv.w * cs1.x;
            *(float4*)&Vs[j][d4 * 4] =
                *(const float4*)(g_V + s * QKV_N + h * DH + d4 * 4);
        }
        __syncthreads();

        // ---- S = Q K^T (2x4 per thread over d=64) ----
        float sreg[2][4] = {};
        #pragma unroll
        for (int d = 0; d < 64; d++) {
            float a0 = Qs[ty][d];
            float a1 = Qs[ty + 16][d];
            float b0 = KWs[tx][d];
            float b1 = KWs[tx + 16][d];
            float b2 = KWs[tx + 32][d];
            float b3 = KWs[tx + 48][d];
            sreg[0][0] = fmaf(a0, b0, sreg[0][0]);
            sreg[0][1] = fmaf(a0, b1, sreg[0][1]);
            sreg[0][2] = fmaf(a0, b2, sreg[0][2]);
            sreg[0][3] = fmaf(a0, b3, sreg[0][3]);
            sreg[1][0] = fmaf(a1, b0, sreg[1][0]);
            sreg[1][1] = fmaf(a1, b1, sreg[1][1]);
            sreg[1][2] = fmaf(a1, b2, sreg[1][2]);
            sreg[1][3] = fmaf(a1, b3, sreg[1][3]);
        }
        __syncthreads();   // Ks reads done; safe to overwrite with W

        // ---- w = softplus(s*scale/denom); causal; w *= sigmoid(SCALE*w) ----
        const bool last = (kt == nkt - 1);
        float ksc[4];
        #pragma unroll
        for (int jj = 0; jj < 4; jj++)
            ksc[jj] = g_kscale[hb * T_SEQ + s0 + tx + 16 * jj];

        #pragma unroll
        for (int ii = 0; ii < 2; ii++) {
            int trow = t0 + ty + 16 * ii;
            #pragma unroll
            for (int jj = 0; jj < 4; jj++) {
                int scol = s0 + tx + 16 * jj;
                float x  = sreg[ii][jj] * ksc[jj];
                float sp = (x > 20.f) ? x : log1pf(__expf(x));
                float w  = sp / (1.f + __expf(-SIGM_SCALE * sp));
                if (last && scol > trow) w = 0.f;
                rowsum[ii] += w;
                KWs[ty + 16 * ii][tx + 16 * jj] = w;
            }
        }
        __syncthreads();

        // ---- acc += W @ V ----
        #pragma unroll
        for (int s = 0; s < 64; s++) {
            float a0 = KWs[ty][s];
            float a1 = KWs[ty + 16][s];
            float b0 = Vs[s][tx];
            float b1 = Vs[s][tx + 16];
            float b2 = Vs[s][tx + 32];
            float b3 = Vs[s][tx + 48];
            acc[0][0] = fmaf(a0, b0, acc[0][0]);
            acc[0][1] = fmaf(a0, b1, acc[0][1]);
            acc[0][2] = fmaf(a0, b2, acc[0][2]);
            acc[0][3] = fmaf(a0, b3, acc[0][3]);
            acc[1][0] = fmaf(a1, b0, acc[1][0]);
            acc[1][1] = fmaf(a1, b1, acc[1][1]);
            acc[1][2] = fmaf(a1, b2, acc[1][2]);
            acc[1][3] = fmaf(a1, b3, acc[1][3]);
        }
    }

    // reduce rowsum across tx (16-lane half-warp groups)
    #pragma unroll
    for (int o = 1; o < 16; o <<= 1) {
        rowsum[0] += __shfl_xor_sync(0xffffffffu, rowsum[0], o);
        rowsum[1] += __shfl_xor_sync(0xffffffffu, rowsum[1], o);
    }

    float sink = tanhf(sink_sc[h]) + 1e-6f;
    #pragma unroll
    for (int ii = 0; ii < 2; ii++) {
        float alpha = 1.f / (rowsum[ii] + sink + 1e-6f);
        int t = t0 + ty + 16 * ii;
        #pragma unroll
        for (int jj = 0; jj < 4; jj++) {
            int d = tx + 16 * jj;
            float o = (acc[ii][jj] + sink * v_nulls[h * DH + d]) * alpha;
            g_ctx[t * QKV_N + h * DH + d] = o;
        }
    }
}

// ---------------- average the 4 branches --------------------------------------
__global__ void avg_kernel()
{
    int idx = blockIdx.x * blockDim.x + threadIdx.x;  // over 1024*256 float4
    if (idx >= T_SEQ * (DMODEL / 4)) return;
    int t  = idx >> 8;
    int c  = (idx & 255) << 2;       // channel = h16*64 + d
    int h16 = c >> 6;
    int d   = c & 63;
    float4 r = make_float4(0.f, 0.f, 0.f, 0.f);
    #pragma unroll
    for (int br = 0; br < 4; br++) {
        float4 v = *(const float4*)(g_ctx + t * QKV_N + (br * 16 + h16) * DH + d);
        r.x += v.x; r.y += v.y; r.z += v.z; r.w += v.w;
    }
    r.x *= 0.25f; r.y *= 0.25f; r.z *= 0.25f; r.w *= 0.25f;
    *(float4*)(g_ctxavg + t * DMODEL + c) = r;
}

// ---------------- launch -------------------------------------------------------
extern "C" void kernel_launch(void* const* d_in, const int* in_sizes, int n_in,
                              void* d_out, int out_size)
{
    const float* X    = (const float*)d_in[0];
    const float* Wq   = (const float*)d_in[1];
    const float* bq   = (const float*)d_in[2];
    const float* Wk   = (const float*)d_in[3];
    const float* bk   = (const float*)d_in[4];
    const float* Wv   = (const float*)d_in[5];
    const float* bv   = (const float*)d_in[6];
    const float* sink = (const float*)d_in[7];
    const float* vnull= (const float*)d_in[8];
    const float* Wo   = (const float*)d_in[9];
    const float* bo   = (const float*)d_in[10];
    float* out        = (float*)d_out;

    float *Q, *K, *V, *CA;
    cudaGetSymbolAddress((void**)&Q,  g_Q);
    cudaGetSymbolAddress((void**)&K,  g_K);
    cudaGetSymbolAddress((void**)&V,  g_V);
    cudaGetSymbolAddress((void**)&CA, g_ctxavg);

    // projections
    sgemm_bias<<<dim3(QKV_N / 128, T_SEQ / 128), 256>>>(X, Wq, bq, Q, QKV_N, DMODEL);
    sgemm_bias<<<dim3(DMODEL / 128, T_SEQ / 128), 256>>>(X, Wk, bk, K, DMODEL, DMODEL);
    sgemm_bias<<<dim3(QKV_N / 128, T_SEQ / 128), 256>>>(X, Wv, bv, V, QKV_N, DMODEL);

    // rope table + key norm scales
    rope_table_kernel<<<(T_SEQ * 32 + 255) / 256, 256>>>();
    kscale_kernel<<<(NHEAD * T_SEQ * 32 + 255) / 256, 256>>>();

    // attention (64 heads x 32 query tiles)
    attn_kernel<<<dim3(32, HTOT), 256>>>(sink, vnull);

    // branch average + output projection
    avg_kernel<<<(T_SEQ * (DMODEL / 4) + 255) / 256, 256>>>();
    sgemm_bias<<<dim3(DMODEL / 128, T_SEQ / 128), 256>>>(CA, Wo, bo, out, DMODEL, DMODEL);
}

// round 3
// speedup vs baseline: 1.3998x; 1.3998x over previous
#include <cuda_runtime.h>
#include <cuda_bf16.h>
#include <cstdint>
#include <cstdio>
#include <math.h>

#define T_SEQ   1024
#define DMODEL  1024
#define NHEAD   16
#define HTOT    64
#define DH      64
#define QKV_N   (HTOT*DH)   /* 4096 */
#define ATTN_SCALE 0.125f
#define SIGM_SCALE 1.8137993642342178f   /* pi/sqrt(3) */

// ---------------- scratch (device globals; no allocation allowed) -------------
__device__ float  g_Q[T_SEQ*QKV_N];
__device__ float  g_K[T_SEQ*DMODEL];
__device__ float  g_V[T_SEQ*QKV_N];
__device__ float  g_kscale[NHEAD*T_SEQ];
__device__ float2 g_rope[T_SEQ*32];
__device__ float  g_ctx[T_SEQ*QKV_N];
__device__ float  g_ctxavg[T_SEQ*DMODEL];

// ---------------- PTX helpers --------------------------------------------------
__device__ __forceinline__ unsigned smem_u32(const void* p) {
    return (unsigned)__cvta_generic_to_shared(p);
}
__device__ __forceinline__ void ldsm_x4(unsigned* r, unsigned a) {
    asm volatile("ldmatrix.sync.aligned.m8n8.x4.shared.b16 {%0,%1,%2,%3}, [%4];"
        : "=r"(r[0]), "=r"(r[1]), "=r"(r[2]), "=r"(r[3]) : "r"(a));
}
__device__ __forceinline__ void ldsm_x4t(unsigned* r, unsigned a) {
    asm volatile("ldmatrix.sync.aligned.m8n8.x4.trans.shared.b16 {%0,%1,%2,%3}, [%4];"
        : "=r"(r[0]), "=r"(r[1]), "=r"(r[2]), "=r"(r[3]) : "r"(a));
}
__device__ __forceinline__ void mma_bf16(float* c, const unsigned* a, const unsigned* b) {
    asm volatile("mma.sync.aligned.m16n8k16.row.col.f32.bf16.bf16.f32 "
        "{%0,%1,%2,%3},{%4,%5,%6,%7},{%8,%9},{%0,%1,%2,%3};"
        : "+f"(c[0]), "+f"(c[1]), "+f"(c[2]), "+f"(c[3])
        : "r"(a[0]), "r"(a[1]), "r"(a[2]), "r"(a[3]), "r"(b[0]), "r"(b[1]));
}

// ---------------- GEMM: C = A(MxK)@B(KxN) + bias, bf16x3 split -----------------
// 128x128 block, BK=16, 256 threads (8 warps), warp tile 64x32.
__global__ __launch_bounds__(256)
void gemm_bf16x3(const float* __restrict__ A, const float* __restrict__ B,
                 const float* __restrict__ bias, float* __restrict__ C,
                 int N, int K)
{
    __shared__ __nv_bfloat16 Ah[128][24];
    __shared__ __nv_bfloat16 Al[128][24];
    __shared__ __nv_bfloat16 Bh[16][136];
    __shared__ __nv_bfloat16 Bl[16][136];

    const int tid  = threadIdx.x;
    const int lane = tid & 31;
    const int warp = tid >> 5;
    const int wm   = warp & 1;
    const int wn   = warp >> 1;
    const int rowBase = blockIdx.y * 128;
    const int colBase = blockIdx.x * 128;

    float acc[4][4][4] = {};

    unsigned aAddrH[4], aAddrL[4], bAddrH[2], bAddrL[2];
    {
        int ar = wm * 64 + (lane & 15);
        int ac = (lane >> 4) * 8;
        for (int ms = 0; ms < 4; ms++) {
            aAddrH[ms] = smem_u32(&Ah[ar + ms * 16][ac]);
            aAddrL[ms] = smem_u32(&Al[ar + ms * 16][ac]);
        }
        int br = lane & 15;
        for (int np = 0; np < 2; np++) {
            int bc = wn * 32 + np * 16 + (lane >> 4) * 8;
            bAddrH[np] = smem_u32(&Bh[br][bc]);
            bAddrL[np] = smem_u32(&Bl[br][bc]);
        }
    }

    for (int k0 = 0; k0 < K; k0 += 16) {
        #pragma unroll
        for (int r = 0; r < 2; r++) {
            int idx = tid + r * 256;
            // A tile: 128x16
            int row = idx >> 2;
            int kc  = (idx & 3) * 4;
            float4 v = *(const float4*)(A + (size_t)(rowBase + row) * K + k0 + kc);
            __nv_bfloat16 hx = __float2bfloat16(v.x);
            __nv_bfloat16 hy = __float2bfloat16(v.y);
            __nv_bfloat16 hz = __float2bfloat16(v.z);
            __nv_bfloat16 hw = __float2bfloat16(v.w);
            Ah[row][kc + 0] = hx;
            Ah[row][kc + 1] = hy;
            Ah[row][kc + 2] = hz;
            Ah[row][kc + 3] = hw;
            Al[row][kc + 0] = __float2bfloat16(v.x - __bfloat162float(hx));
            Al[row][kc + 1] = __float2bfloat16(v.y - __bfloat162float(hy));
            Al[row][kc + 2] = __float2bfloat16(v.z - __bfloat162float(hz));
            Al[row][kc + 3] = __float2bfloat16(v.w - __bfloat162float(hw));
            // B tile: 16x128
            int kr = idx >> 5;
            int nc = (idx & 31) * 4;
            float4 u = *(const float4*)(B + (size_t)(k0 + kr) * N + colBase + nc);
            __nv_bfloat16 px = __float2bfloat16(u.x);
            __nv_bfloat16 py = __float2bfloat16(u.y);
            __nv_bfloat16 pz = __float2bfloat16(u.z);
            __nv_bfloat16 pw = __float2bfloat16(u.w);
            Bh[kr][nc + 0] = px;
            Bh[kr][nc + 1] = py;
            Bh[kr][nc + 2] = pz;
            Bh[kr][nc + 3] = pw;
            Bl[kr][nc + 0] = __float2bfloat16(u.x - __bfloat162float(px));
            Bl[kr][nc + 1] = __float2bfloat16(u.y - __bfloat162float(py));
            Bl[kr][nc + 2] = __float2bfloat16(u.z - __bfloat162float(pz));
            Bl[kr][nc + 3] = __float2bfloat16(u.w - __bfloat162float(pw));
        }
        __syncthreads();

        unsigned aH[4][4], aL[4][4], bH[2][4], bL[2][4];
        #pragma unroll
        for (int ms = 0; ms < 4; ms++) {
            ldsm_x4(aH[ms], aAddrH[ms]);
            ldsm_x4(aL[ms], aAddrL[ms]);
        }
        #pragma unroll
        for (int np = 0; np < 2; np++) {
            ldsm_x4t(bH[np], bAddrH[np]);
            ldsm_x4t(bL[np], bAddrL[np]);
        }

        #pragma unroll
        for (int ms = 0; ms < 4; ms++) {
            #pragma unroll
            for (int ns = 0; ns < 4; ns++) {
                const unsigned* bh = &bH[ns >> 1][(ns & 1) * 2];
                const unsigned* bl = &bL[ns >> 1][(ns & 1) * 2];
                mma_bf16(acc[ms][ns], aH[ms], bh);
                mma_bf16(acc[ms][ns], aH[ms], bl);
                mma_bf16(acc[ms][ns], aL[ms], bh);
            }
        }
        __syncthreads();
    }

    const int g  = lane >> 2;
    const int cc = (lane & 3) * 2;
    #pragma unroll
    for (int ms = 0; ms < 4; ms++) {
        #pragma unroll
        for (int ns = 0; ns < 4; ns++) {
            int row = rowBase + wm * 64 + ms * 16 + g;
            int col = colBase + wn * 32 + ns * 8 + cc;
            float2 bv = *(const float2*)(bias + col);
            float2 o0, o1;
            o0.x = acc[ms][ns][0] + bv.x;
            o0.y = acc[ms][ns][1] + bv.y;
            o1.x = acc[ms][ns][2] + bv.x;
            o1.y = acc[ms][ns][3] + bv.y;
            *(float2*)(C + (size_t)row * N + col)       = o0;
            *(float2*)(C + (size_t)(row + 8) * N + col) = o1;
        }
    }
}

// ---------------- RoPE cos/sin table ------------------------------------------
__global__ void rope_table_kernel()
{
    int idx = blockIdx.x * blockDim.x + threadIdx.x;
    if (idx >= T_SEQ * 32) return;
    int t = idx >> 5;
    int p = idx & 31;
    float inv = expf(-(float)p * 0.28782313662425575f);
    float ang = (float)t * inv;
    float s, c;
    sincosf(ang, &s, &c);
    g_rope[idx] = make_float2(c, s);
}

// ---------------- key norm scale (rope preserves |k|^2) ------------------------
__global__ void kscale_kernel()
{
    int gw   = (blockIdx.x * blockDim.x + threadIdx.x) >> 5;
    int lane = threadIdx.x & 31;
    if (gw >= NHEAD * T_SEQ) return;
    int hb = gw >> 10;
    int t  = gw & 1023;
    const float* kp = g_K + (size_t)t * DMODEL + hb * DH;
    float2 v = *(const float2*)(kp + 2 * lane);
    float s = v.x * v.x + v.y * v.y;
    #pragma unroll
    for (int o = 16; o; o >>= 1) s += __shfl_xor_sync(0xffffffffu, s, o);
    if (lane == 0)
        g_kscale[hb * T_SEQ + t] = ATTN_SCALE / sqrtf(fmaxf(s, 1e-6f));
}

// ---------------- attention: block = (64 queries, 1 head), 128 threads ---------
// Thread tile 4 rows x 8 cols; all inner-loop smem traffic is float4.
#define AT_STRIDE 68
__global__ __launch_bounds__(128)
void attn_kernel(const float* __restrict__ sink_sc,
                 const float* __restrict__ v_nulls)
{
    extern __shared__ float sm[];
    float* Qt = sm;                       // [64][68] roped Q^T (d, i)
    float* KW = sm + 64 * AT_STRIDE;      // [64][68] roped K^T (d, j) -> W^T (j, i)
    float* Vs = sm + 2 * 64 * AT_STRIDE;  // [64][68] V (s, d')

    const int qi  = blockIdx.x;
    const int h   = blockIdx.y;
    const int hb  = h & 15;
    const int tid = threadIdx.x;
    const int tx  = tid & 7;
    const int ty  = tid >> 3;
    const int t0  = qi * 64;
    const int i0  = ty * 4;
    const int j0  = tx * 8;

    // ---- load + rope + transpose Q tile (64x64) ----
    #pragma unroll
    for (int r = 0; r < 8; r++) {
        int idx = tid + r * 128;
        int i   = idx >> 4;
        int d4  = idx & 15;
        int t   = t0 + i;
        float4 v  = *(const float4*)(g_Q + (size_t)t * QKV_N + h * DH + d4 * 4);
        float2 c0 = g_rope[t * 32 + 2 * d4];
        float2 c1 = g_rope[t * 32 + 2 * d4 + 1];
        Qt[(2 * d4)      * AT_STRIDE + i] = v.x * c0.x - v.y * c0.y;
        Qt[(2 * d4 + 1)  * AT_STRIDE + i] = v.z * c1.x - v.w * c1.y;
        Qt[(2 * d4 + 32) * AT_STRIDE + i] = v.x * c0.y + v.y * c0.x;
        Qt[(2 * d4 + 33) * AT_STRIDE + i] = v.z * c1.y + v.w * c1.x;
    }

    float acc[4][8] = {};
    float rowsum[4] = {};

    for (int kt = 0; kt <= qi; kt++) {
        const int s0 = kt * 64;
        __syncthreads();

        // ---- load + rope K^T, load V ----
        #pragma unroll
        for (int r = 0; r < 8; r++) {
            int idx = tid + r * 128;
            int j   = idx >> 4;
            int d4  = idx & 15;
            int s   = s0 + j;
            float4 kv = *(const float4*)(g_K + (size_t)s * DMODEL + hb * DH + d4 * 4);
            float2 c0 = g_rope[s * 32 + 2 * d4];
            float2 c1 = g_rope[s * 32 + 2 * d4 + 1];
            KW[(2 * d4)      * AT_STRIDE + j] = kv.x * c0.x - kv.y * c0.y;
            KW[(2 * d4 + 1)  * AT_STRIDE + j] = kv.z * c1.x - kv.w * c1.y;
            KW[(2 * d4 + 32) * AT_STRIDE + j] = kv.x * c0.y + kv.y * c0.x;
            KW[(2 * d4 + 33) * AT_STRIDE + j] = kv.z * c1.y + kv.w * c1.x;
            *(float4*)&Vs[j * AT_STRIDE + d4 * 4] =
                *(const float4*)(g_V + (size_t)s * QKV_N + h * DH + d4 * 4);
        }
        __syncthreads();

        // ---- S = Q K^T : 4x8 per thread over d ----
        float sreg[4][8] = {};
        #pragma unroll
        for (int d = 0; d < 64; d++) {
            float4 a  = *(float4*)&Qt[d * AT_STRIDE + i0];
            float4 b0 = *(float4*)&KW[d * AT_STRIDE + j0];
            float4 b1 = *(float4*)&KW[d * AT_STRIDE + j0 + 4];
            float av[4] = {a.x, a.y, a.z, a.w};
            float bv[8] = {b0.x, b0.y, b0.z, b0.w, b1.x, b1.y, b1.z, b1.w};
            #pragma unroll
            for (int ii = 0; ii < 4; ii++) {
                #pragma unroll
                for (int jj = 0; jj < 8; jj++) {
                    sreg[ii][jj] = fmaf(av[ii], bv[jj], sreg[ii][jj]);
                }
            }
        }
        __syncthreads();

        // ---- activation + causal mask; store W^T into KW ----
        float ksc[8];
        *(float4*)&ksc[0] = *(const float4*)(g_kscale + hb * T_SEQ + s0 + j0);
        *(float4*)&ksc[4] = *(const float4*)(g_kscale + hb * T_SEQ + s0 + j0 + 4);
        const bool diag = (kt == qi);
        #pragma unroll
        for (int ii = 0; ii < 4; ii++) {
            #pragma unroll
            for (int jj = 0; jj < 8; jj++) {
                float x  = sreg[ii][jj] * ksc[jj];
                float sp = (x > 15.f) ? x : __logf(1.f + __expf(x));
                float w  = __fdividef(sp, 1.f + __expf(-SIGM_SCALE * sp));
                if (diag && (j0 + jj > i0 + ii)) w = 0.f;
                rowsum[ii] += w;
                KW[(j0 + jj) * AT_STRIDE + i0 + ii] = w;
            }
        }
        __syncthreads();

        // ---- acc += W V : over s ----
        #pragma unroll
        for (int s = 0; s < 64; s++) {
            float4 a  = *(float4*)&KW[s * AT_STRIDE + i0];
            float4 b0 = *(float4*)&Vs[s * AT_STRIDE + j0];
            float4 b1 = *(float4*)&Vs[s * AT_STRIDE + j0 + 4];
            float av[4] = {a.x, a.y, a.z, a.w};
            float bv[8] = {b0.x, b0.y, b0.z, b0.w, b1.x, b1.y, b1.z, b1.w};
            #pragma unroll
            for (int ii = 0; ii < 4; ii++) {
                #pragma unroll
                for (int jj = 0; jj < 8; jj++) {
                    acc[ii][jj] = fmaf(av[ii], bv[jj], acc[ii][jj]);
                }
            }
        }
    }

    // rowsum reduce across the 8 tx lanes
    #pragma unroll
    for (int o = 1; o < 8; o <<= 1) {
        #pragma unroll
        for (int ii = 0; ii < 4; ii++) {
            rowsum[ii] += __shfl_xor_sync(0xffffffffu, rowsum[ii], o);
        }
    }

    float sink = tanhf(sink_sc[h]) + 1e-6f;
    float vn[8];
    *(float4*)&vn[0] = *(const float4*)(v_nulls + h * DH + j0);
    *(float4*)&vn[4] = *(const float4*)(v_nulls + h * DH + j0 + 4);
    #pragma unroll
    for (int ii = 0; ii < 4; ii++) {
        float alpha = __fdividef(1.f, rowsum[ii] + sink + 1e-6f);
        int t = t0 + i0 + ii;
        float4 o0, o1;
        o0.x = (acc[ii][0] + sink * vn[0]) * alpha;
        o0.y = (acc[ii][1] + sink * vn[1]) * alpha;
        o0.z = (acc[ii][2] + sink * vn[2]) * alpha;
        o0.w = (acc[ii][3] + sink * vn[3]) * alpha;
        o1.x = (acc[ii][4] + sink * vn[4]) * alpha;
        o1.y = (acc[ii][5] + sink * vn[5]) * alpha;
        o1.z = (acc[ii][6] + sink * vn[6]) * alpha;
        o1.w = (acc[ii][7] + sink * vn[7]) * alpha;
        *(float4*)(g_ctx + (size_t)t * QKV_N + h * DH + j0)     = o0;
        *(float4*)(g_ctx + (size_t)t * QKV_N + h * DH + j0 + 4) = o1;
    }
}

// ---------------- average the 4 branches --------------------------------------
__global__ void avg_kernel()
{
    int idx = blockIdx.x * blockDim.x + threadIdx.x;
    if (idx >= T_SEQ * (DMODEL / 4)) return;
    int t   = idx >> 8;
    int c   = (idx & 255) << 2;
    int h16 = c >> 6;
    int d   = c & 63;
    float4 r = make_float4(0.f, 0.f, 0.f, 0.f);
    #pragma unroll
    for (int br = 0; br < 4; br++) {
        float4 v = *(const float4*)(g_ctx + (size_t)t * QKV_N + (br * 16 + h16) * DH + d);
        r.x += v.x;
        r.y += v.y;
        r.z += v.z;
        r.w += v.w;
    }
    r.x *= 0.25f;
    r.y *= 0.25f;
    r.z *= 0.25f;
    r.w *= 0.25f;
    *(float4*)(g_ctxavg + (size_t)t * DMODEL + c) = r;
}

// ---------------- launch -------------------------------------------------------
extern "C" void kernel_launch(void* const* d_in, const int* in_sizes, int n_in,
                              void* d_out, int out_size)
{
    const float* X     = (const float*)d_in[0];
    const float* Wq    = (const float*)d_in[1];
    const float* bq    = (const float*)d_in[2];
    const float* Wk    = (const float*)d_in[3];
    const float* bk    = (const float*)d_in[4];
    const float* Wv    = (const float*)d_in[5];
    const float* bv    = (const float*)d_in[6];
    const float* sink  = (const float*)d_in[7];
    const float* vnull = (const float*)d_in[8];
    const float* Wo    = (const float*)d_in[9];
    const float* bo    = (const float*)d_in[10];
    float* out         = (float*)d_out;

    float *Q, *K, *V, *CA;
    cudaGetSymbolAddress((void**)&Q,  g_Q);
    cudaGetSymbolAddress((void**)&K,  g_K);
    cudaGetSymbolAddress((void**)&V,  g_V);
    cudaGetSymbolAddress((void**)&CA, g_ctxavg);

    const int attn_smem = 3 * 64 * AT_STRIDE * sizeof(float);   // 52224 B
    cudaFuncSetAttribute(attn_kernel,
                         cudaFuncAttributeMaxDynamicSharedMemorySize, attn_smem);

    gemm_bf16x3<<<dim3(QKV_N / 128, T_SEQ / 128), 256>>>(X, Wq, bq, Q, QKV_N, DMODEL);
    gemm_bf16x3<<<dim3(DMODEL / 128, T_SEQ / 128), 256>>>(X, Wk, bk, K, DMODEL, DMODEL);
    gemm_bf16x3<<<dim3(QKV_N / 128, T_SEQ / 128), 256>>>(X, Wv, bv, V, QKV_N, DMODEL);

    rope_table_kernel<<<(T_SEQ * 32 + 255) / 256, 256>>>();
    kscale_kernel<<<(NHEAD * T_SEQ * 32 + 255) / 256, 256>>>();

    attn_kernel<<<dim3(16, HTOT), 128, attn_smem>>>(sink, vnull);

    avg_kernel<<<(T_SEQ * (DMODEL / 4) + 255) / 256, 256>>>();
    gemm_bf16x3<<<dim3(DMODEL / 128, T_SEQ / 128), 256>>>(CA, Wo, bo, out, DMODEL, DMODEL);
}

// round 12
// speedup vs baseline: 1.4549x; 1.0393x over previous
#include <cuda_runtime.h>
#include <cuda_bf16.h>
#include <cstdint>
#include <math.h>

#define T_SEQ   1024
#define DMODEL  1024
#define NHEAD   16
#define HTOT    64
#define DH      64
#define QKV_N   (HTOT*DH)   /* 4096 */
#define KDIM    1024
#define ATTN_SCALE 0.125f
#define SIGM_SCALE 1.8137993642342178f   /* pi/sqrt(3) */

// ---------------- scratch (device globals; no allocation allowed) -------------
__device__ float  g_Q[T_SEQ*QKV_N];
__device__ float  g_K[T_SEQ*DMODEL];
__device__ float  g_V[T_SEQ*QKV_N];
__device__ float  g_kscale[NHEAD*T_SEQ];
__device__ float2 g_rope[T_SEQ*32];
__device__ float  g_ctx[T_SEQ*QKV_N];
__device__ float  g_ctxavg[T_SEQ*DMODEL];

// bf16 hi/lo split operands (g_Xh/g_Xl reused for the context split after attn)
__device__ __nv_bfloat16 g_Xh[T_SEQ*KDIM],    g_Xl[T_SEQ*KDIM];
__device__ __nv_bfloat16 g_WqTh[QKV_N*KDIM],  g_WqTl[QKV_N*KDIM];
__device__ __nv_bfloat16 g_WkTh[DMODEL*KDIM], g_WkTl[DMODEL*KDIM];
__device__ __nv_bfloat16 g_WvTh[QKV_N*KDIM],  g_WvTl[QKV_N*KDIM];
__device__ __nv_bfloat16 g_WoTh[DMODEL*KDIM], g_WoTl[DMODEL*KDIM];

// ---------------- PTX helpers --------------------------------------------------
__device__ __forceinline__ unsigned smem_u32(const void* p) {
    return (unsigned)__cvta_generic_to_shared(p);
}
__device__ __forceinline__ void ldsm_x4(unsigned* r, unsigned a) {
    asm volatile("ldmatrix.sync.aligned.m8n8.x4.shared.b16 {%0,%1,%2,%3}, [%4];"
        : "=r"(r[0]), "=r"(r[1]), "=r"(r[2]), "=r"(r[3]) : "r"(a));
}
__device__ __forceinline__ void mma_bf16(float* c, const unsigned* a,
                                         unsigned b0, unsigned b1) {
    asm volatile("mma.sync.aligned.m16n8k16.row.col.f32.bf16.bf16.f32 "
        "{%0,%1,%2,%3},{%4,%5,%6,%7},{%8,%9},{%0,%1,%2,%3};"
        : "+f"(c[0]), "+f"(c[1]), "+f"(c[2]), "+f"(c[3])
        : "r"(a[0]), "r"(a[1]), "r"(a[2]), "r"(a[3]), "r"(b0), "r"(b1));
}
__device__ __forceinline__ void cp16(unsigned dst, const void* src) {
    asm volatile("cp.async.cg.shared.global [%0], [%1], 16;"
        :: "r"(dst), "l"(src) : "memory");
}
__device__ __forceinline__ void cp_commit() {
    asm volatile("cp.async.commit_group;" ::: "memory");
}

// ---------------- split kernels -------------------------------------------------
__global__ void esplit_kernel(const float* __restrict__ A,
                              __nv_bfloat16* __restrict__ H,
                              __nv_bfloat16* __restrict__ L, int n)
{
    int i = (blockIdx.x * blockDim.x + threadIdx.x) * 4;
    if (i >= n) return;
    float4 v = *(const float4*)(A + i);
    __nv_bfloat16 hx = __float2bfloat16(v.x);
    __nv_bfloat16 hy = __float2bfloat16(v.y);
    __nv_bfloat16 hz = __float2bfloat16(v.z);
    __nv_bfloat16 hw = __float2bfloat16(v.w);
    H[i + 0] = hx; H[i + 1] = hy; H[i + 2] = hz; H[i + 3] = hw;
    L[i + 0] = __float2bfloat16(v.x - __bfloat162float(hx));
    L[i + 1] = __float2bfloat16(v.y - __bfloat162float(hy));
    L[i + 2] = __float2bfloat16(v.z - __bfloat162float(hz));
    L[i + 3] = __float2bfloat16(v.w - __bfloat162float(hw));
}

// transpose + split: W[K][N] fp32 -> Th/Tl [N][K] bf16
__global__ __launch_bounds__(256)
void tsplit_kernel(const float* __restrict__ W,
                   __nv_bfloat16* __restrict__ Th,
                   __nv_bfloat16* __restrict__ Tl, int K, int N)
{
    __shared__ float t[32][33];
    const int tid = threadIdx.x;
    const int tx = tid & 31, ty = tid >> 5;
    const int k0 = blockIdx.y * 32, n0 = blockIdx.x * 32;
    #pragma unroll
    for (int r = 0; r < 4; r++) {
        int k = k0 + ty + r * 8;
        t[ty + r * 8][tx] = W[(size_t)k * N + n0 + tx];
    }
    __syncthreads();
    #pragma unroll
    for (int r = 0; r < 4; r++) {
        int n = n0 + ty + r * 8;
        int k = k0 + tx;
        float v = t[tx][ty + r * 8];
        __nv_bfloat16 h = __float2bfloat16(v);
        Th[(size_t)n * K + k] = h;
        Tl[(size_t)n * K + k] = __float2bfloat16(v - __bfloat162float(h));
    }
}

// ---------------- mma.sync GEMM: C = Ahl @ Bhl^T + bias ------------------------
// A: [M][K] bf16 hi/lo, B: [N][K] bf16 hi/lo pre-transposed. CTA 128x128, BK=32,
// cp.async double buffer, bf16x3 products.
#define TILE_B  8192                 /* 128 rows x 64B */
#define STG_B   (4*TILE_B)           /* Ah, Al, Bh, Bl  */
__global__ __launch_bounds__(256)
void gemm_mma(const __nv_bfloat16* __restrict__ Ah, const __nv_bfloat16* __restrict__ Al,
              const __nv_bfloat16* __restrict__ Bh, const __nv_bfloat16* __restrict__ Bl,
              const float* __restrict__ bias, float* __restrict__ C, int N)
{
    extern __shared__ char smem[];
    const int tid  = threadIdx.x;
    const int lane = tid & 31;
    const int warp = tid >> 5;
    const int wm   = warp & 1;
    const int wn   = warp >> 1;
    const int rowBase = blockIdx.y * 128;
    const int colBase = blockIdx.x * 128;
    const __nv_bfloat16* srcs[4] = { Ah, Al, Bh, Bl };

    auto load_stage = [&](int ch, int stg) {
        char* sp = smem + stg * STG_B;
        #pragma unroll
        for (int i = 0; i < 8; i++) {
            int idx = tid + i * 256;
            int t   = idx >> 9;
            int rem = idx & 511;
            int row = rem >> 2;
            int c   = rem & 3;
            int gr  = (t < 2 ? rowBase : colBase) + row;
            const __nv_bfloat16* g = srcs[t] + (size_t)gr * KDIM + ch * 32 + c * 8;
            unsigned dst = smem_u32(sp + t * TILE_B + row * 64 +
                                    ((c ^ ((row >> 1) & 3)) * 16));
            cp16(dst, g);
        }
        cp_commit();
    };

    float acc[4][4][4] = {};
    const int NCH = KDIM / 32;   // 32

    load_stage(0, 0);
    for (int ch = 0; ch < NCH; ch++) {
        const int stg = ch & 1;
        if (ch + 1 < NCH) {
            load_stage(ch + 1, stg ^ 1);
            asm volatile("cp.async.wait_group 1;" ::: "memory");
        } else {
            asm volatile("cp.async.wait_group 0;" ::: "memory");
        }
        __syncthreads();

        char* sp = smem + stg * STG_B;
        #pragma unroll
        for (int ks = 0; ks < 2; ks++) {
            unsigned aH[4][4], aL[4][4], bH[2][4], bL[2][4];
            const int half  = lane >> 4;
            const int chunk = ks * 2 + half;
            #pragma unroll
            for (int ms = 0; ms < 4; ms++) {
                int row = wm * 64 + (lane & 15) + ms * 16;
                unsigned off = row * 64 + ((chunk ^ ((row >> 1) & 3)) * 16);
                ldsm_x4(aH[ms], smem_u32(sp + off));
                ldsm_x4(aL[ms], smem_u32(sp + TILE_B + off));
            }
            #pragma unroll
            for (int np = 0; np < 2; np++) {
                int row = wn * 32 + (lane & 15) + np * 16;
                unsigned off = row * 64 + ((chunk ^ ((row >> 1) & 3)) * 16);
                ldsm_x4(bH[np], smem_u32(sp + 2 * TILE_B + off));
                ldsm_x4(bL[np], smem_u32(sp + 3 * TILE_B + off));
            }
            #pragma unroll
            for (int ms = 0; ms < 4; ms++) {
                #pragma unroll
                for (int bg = 0; bg < 4; bg++) {
                    const int np = bg >> 1, gg = bg & 1;
                    mma_bf16(acc[ms][bg], aH[ms], bH[np][gg], bH[np][gg + 2]);
                    mma_bf16(acc[ms][bg], aH[ms], bL[np][gg], bL[np][gg + 2]);
                    mma_bf16(acc[ms][bg], aL[ms], bH[np][gg], bH[np][gg + 2]);
                }
            }
        }
        __syncthreads();
    }

    // ---- epilogue ----
    #pragma unroll
    for (int ms = 0; ms < 4; ms++) {
        int r0 = rowBase + wm * 64 + ms * 16 + (lane >> 2);
        #pragma unroll
        for (int bg = 0; bg < 4; bg++) {
            int col = colBase + wn * 32 + (bg >> 1) * 16 + (bg & 1) * 8 + (lane & 3) * 2;
            float2 bv = *(const float2*)(bias + col);
            float2 o0, o1;
            o0.x = acc[ms][bg][0] + bv.x;
            o0.y = acc[ms][bg][1] + bv.y;
            o1.x = acc[ms][bg][2] + bv.x;
            o1.y = acc[ms][bg][3] + bv.y;
            *(float2*)(C + (size_t)r0 * N + col)       = o0;
            *(float2*)(C + (size_t)(r0 + 8) * N + col) = o1;
        }
    }
}

// ---------------- RoPE cos/sin table ------------------------------------------
__global__ void rope_table_kernel()
{
    int idx = blockIdx.x * blockDim.x + threadIdx.x;
    if (idx >= T_SEQ * 32) return;
    int t = idx >> 5;
    int p = idx & 31;
    float inv = expf(-(float)p * 0.28782313662425575f);
    float ang = (float)t * inv;
    float s, c;
    sincosf(ang, &s, &c);
    g_rope[idx] = make_float2(c, s);
}

// ---------------- key norm scale (rope preserves |k|^2) ------------------------
__global__ void kscale_kernel()
{
    int gw   = (blockIdx.x * blockDim.x + threadIdx.x) >> 5;
    int lane = threadIdx.x & 31;
    if (gw >= NHEAD * T_SEQ) return;
    int hb = gw >> 10;
    int t  = gw & 1023;
    const float* kp = g_K + (size_t)t * DMODEL + hb * DH;
    float2 v = *(const float2*)(kp + 2 * lane);
    float s = v.x * v.x + v.y * v.y;
    #pragma unroll
    for (int o = 16; o; o >>= 1) s += __shfl_xor_sync(0xffffffffu, s, o);
    if (lane == 0)
        g_kscale[hb * T_SEQ + t] = ATTN_SCALE / sqrtf(fmaxf(s, 1e-6f));
}

// ---------------- attention: block = (64 queries, 1 head), 128 threads ---------
#define AT_STRIDE 68
__global__ __launch_bounds__(128)
void attn_kernel(const float* __restrict__ sink_sc,
                 const float* __restrict__ v_nulls)
{
    extern __shared__ float sm[];
    float* Qt = sm;
    float* KW = sm + 64 * AT_STRIDE;
    float* Vs = sm + 2 * 64 * AT_STRIDE;

    const int qi  = blockIdx.x;
    const int h   = blockIdx.y;
    const int hb  = h & 15;
    const int tid = threadIdx.x;
    const int tx  = tid & 7;
    const int ty  = tid >> 3;
    const int t0  = qi * 64;
    const int i0  = ty * 4;
    const int j0  = tx * 8;

    #pragma unroll
    for (int r = 0; r < 8; r++) {
        int idx = tid + r * 128;
        int i   = idx >> 4;
        int d4  = idx & 15;
        int t   = t0 + i;
        float4 v  = *(const float4*)(g_Q + (size_t)t * QKV_N + h * DH + d4 * 4);
        float2 c0 = g_rope[t * 32 + 2 * d4];
        float2 c1 = g_rope[t * 32 + 2 * d4 + 1];
        Qt[(2 * d4)      * AT_STRIDE + i] = v.x * c0.x - v.y * c0.y;
        Qt[(2 * d4 + 1)  * AT_STRIDE + i] = v.z * c1.x - v.w * c1.y;
        Qt[(2 * d4 + 32) * AT_STRIDE + i] = v.x * c0.y + v.y * c0.x;
        Qt[(2 * d4 + 33) * AT_STRIDE + i] = v.z * c1.y + v.w * c1.x;
    }

    float acc[4][8] = {};
    float rowsum[4] = {};

    for (int kt = 0; kt <= qi; kt++) {
        const int s0 = kt * 64;
        __syncthreads();

        #pragma unroll
        for (int r = 0; r < 8; r++) {
            int idx = tid + r * 128;
            int j   = idx >> 4;
            int d4  = idx & 15;
            int s   = s0 + j;
            float4 kv = *(const float4*)(g_K + (size_t)s * DMODEL + hb * DH + d4 * 4);
            float2 c0 = g_rope[s * 32 + 2 * d4];
            float2 c1 = g_rope[s * 32 + 2 * d4 + 1];
            KW[(2 * d4)      * AT_STRIDE + j] = kv.x * c0.x - kv.y * c0.y;
            KW[(2 * d4 + 1)  * AT_STRIDE + j] = kv.z * c1.x - kv.w * c1.y;
            KW[(2 * d4 + 32) * AT_STRIDE + j] = kv.x * c0.y + kv.y * c0.x;
            KW[(2 * d4 + 33) * AT_STRIDE + j] = kv.z * c1.y + kv.w * c1.x;
            *(float4*)&Vs[j * AT_STRIDE + d4 * 4] =
                *(const float4*)(g_V + (size_t)s * QKV_N + h * DH + d4 * 4);
        }
        __syncthreads();

        float sreg[4][8] = {};
        #pragma unroll
        for (int d = 0; d < 64; d++) {
            float4 a  = *(float4*)&Qt[d * AT_STRIDE + i0];
            float4 b0 = *(float4*)&KW[d * AT_STRIDE + j0];
            float4 b1 = *(float4*)&KW[d * AT_STRIDE + j0 + 4];
            float av[4] = {a.x, a.y, a.z, a.w};
            float bv[8] = {b0.x, b0.y, b0.z, b0.w, b1.x, b1.y, b1.z, b1.w};
            #pragma unroll
            for (int ii = 0; ii < 4; ii++)
                #pragma unroll
                for (int jj = 0; jj < 8; jj++)
                    sreg[ii][jj] = fmaf(av[ii], bv[jj], sreg[ii][jj]);
        }
        __syncthreads();

        float ksc[8];
        *(float4*)&ksc[0] = *(const float4*)(g_kscale + hb * T_SEQ + s0 + j0);
        *(float4*)&ksc[4] = *(const float4*)(g_kscale + hb * T_SEQ + s0 + j0 + 4);
        const bool diag = (kt == qi);
        #pragma unroll
        for (int ii = 0; ii < 4; ii++) {
            #pragma unroll
            for (int jj = 0; jj < 8; jj++) {
                float x  = sreg[ii][jj] * ksc[jj];
                float sp = (x > 15.f) ? x : __logf(1.f + __expf(x));
                float w  = __fdividef(sp, 1.f + __expf(-SIGM_SCALE * sp));
                if (diag && (j0 + jj > i0 + ii)) w = 0.f;
                rowsum[ii] += w;
                KW[(j0 + jj) * AT_STRIDE + i0 + ii] = w;
            }
        }
        __syncthreads();

        #pragma unroll
        for (int s = 0; s < 64; s++) {
            float4 a  = *(float4*)&KW[s * AT_STRIDE + i0];
            float4 b0 = *(float4*)&Vs[s * AT_STRIDE + j0];
            float4 b1 = *(float4*)&Vs[s * AT_STRIDE + j0 + 4];
            float av[4] = {a.x, a.y, a.z, a.w};
            float bv[8] = {b0.x, b0.y, b0.z, b0.w, b1.x, b1.y, b1.z, b1.w};
            #pragma unroll
            for (int ii = 0; ii < 4; ii++)
                #pragma unroll
                for (int jj = 0; jj < 8; jj++)
                    acc[ii][jj] = fmaf(av[ii], bv[jj], acc[ii][jj]);
        }
    }

    #pragma unroll
    for (int o = 1; o < 8; o <<= 1)
        #pragma unroll
        for (int ii = 0; ii < 4; ii++)
            rowsum[ii] += __shfl_xor_sync(0xffffffffu, rowsum[ii], o);

    float sink = tanhf(sink_sc[h]) + 1e-6f;
    float vn[8];
    *(float4*)&vn[0] = *(const float4*)(v_nulls + h * DH + j0);
    *(float4*)&vn[4] = *(const float4*)(v_nulls + h * DH + j0 + 4);
    #pragma unroll
    for (int ii = 0; ii < 4; ii++) {
        float alpha = __fdividef(1.f, rowsum[ii] + sink + 1e-6f);
        int t = t0 + i0 + ii;
        float4 o0, o1;
        o0.x = (acc[ii][0] + sink * vn[0]) * alpha;
        o0.y = (acc[ii][1] + sink * vn[1]) * alpha;
        o0.z = (acc[ii][2] + sink * vn[2]) * alpha;
        o0.w = (acc[ii][3] + sink * vn[3]) * alpha;
        o1.x = (acc[ii][4] + sink * vn[4]) * alpha;
        o1.y = (acc[ii][5] + sink * vn[5]) * alpha;
        o1.z = (acc[ii][6] + sink * vn[6]) * alpha;
        o1.w = (acc[ii][7] + sink * vn[7]) * alpha;
        *(float4*)(g_ctx + (size_t)t * QKV_N + h * DH + j0)     = o0;
        *(float4*)(g_ctx + (size_t)t * QKV_N + h * DH + j0 + 4) = o1;
    }
}

// ---------------- average the 4 branches --------------------------------------
__global__ void avg_kernel()
{
    int idx = blockIdx.x * blockDim.x + threadIdx.x;
    if (idx >= T_SEQ * (DMODEL / 4)) return;
    int t   = idx >> 8;
    int c   = (idx & 255) << 2;
    int h16 = c >> 6;
    int d   = c & 63;
    float4 r = make_float4(0.f, 0.f, 0.f, 0.f);
    #pragma unroll
    for (int br = 0; br < 4; br++) {
        float4 v = *(const float4*)(g_ctx + (size_t)t * QKV_N + (br * 16 + h16) * DH + d);
        r.x += v.x; r.y += v.y; r.z += v.z; r.w += v.w;
    }
    r.x *= 0.25f; r.y *= 0.25f; r.z *= 0.25f; r.w *= 0.25f;
    *(float4*)(g_ctxavg + (size_t)t * DMODEL + c) = r;
}

// ---------------- launch -------------------------------------------------------
extern "C" void kernel_launch(void* const* d_in, const int* in_sizes, int n_in,
                              void* d_out, int out_size)
{
    const float* X     = (const float*)d_in[0];
    const float* Wq    = (const float*)d_in[1];
    const float* bq    = (const float*)d_in[2];
    const float* Wk    = (const float*)d_in[3];
    const float* bk    = (const float*)d_in[4];
    const float* Wv    = (const float*)d_in[5];
    const float* bv    = (const float*)d_in[6];
    const float* sink  = (const float*)d_in[7];
    const float* vnull = (const float*)d_in[8];
    const float* Wo    = (const float*)d_in[9];
    const float* bo    = (const float*)d_in[10];
    float* out         = (float*)d_out;

    float *Q, *K, *V, *CA;
    cudaGetSymbolAddress((void**)&Q,  g_Q);
    cudaGetSymbolAddress((void**)&K,  g_K);
    cudaGetSymbolAddress((void**)&V,  g_V);
    cudaGetSymbolAddress((void**)&CA, g_ctxavg);
    __nv_bfloat16 *Xh, *Xl, *WqTh, *WqTl, *WkTh, *WkTl, *WvTh, *WvTl, *WoTh, *WoTl;
    cudaGetSymbolAddress((void**)&Xh,   g_Xh);
    cudaGetSymbolAddress((void**)&Xl,   g_Xl);
    cudaGetSymbolAddress((void**)&WqTh, g_WqTh);
    cudaGetSymbolAddress((void**)&WqTl, g_WqTl);
    cudaGetSymbolAddress((void**)&WkTh, g_WkTh);
    cudaGetSymbolAddress((void**)&WkTl, g_WkTl);
    cudaGetSymbolAddress((void**)&WvTh, g_WvTh);
    cudaGetSymbolAddress((void**)&WvTl, g_WvTl);
    cudaGetSymbolAddress((void**)&WoTh, g_WoTh);
    cudaGetSymbolAddress((void**)&WoTl, g_WoTl);

    const int attn_smem = 3 * 64 * AT_STRIDE * sizeof(float);   // 52224
    cudaFuncSetAttribute(attn_kernel,
                         cudaFuncAttributeMaxDynamicSharedMemorySize, attn_smem);
    const int gemm_smem = 2 * STG_B;                            // 65536
    cudaFuncSetAttribute(gemm_mma,
                         cudaFuncAttributeMaxDynamicSharedMemorySize, gemm_smem);

    // one-time operand splits
    esplit_kernel<<<T_SEQ * KDIM / 4 / 256, 256>>>(X, Xh, Xl, T_SEQ * KDIM);
    tsplit_kernel<<<dim3(QKV_N / 32, KDIM / 32), 256>>>(Wq, WqTh, WqTl, KDIM, QKV_N);
    tsplit_kernel<<<dim3(DMODEL / 32, KDIM / 32), 256>>>(Wk, WkTh, WkTl, KDIM, DMODEL);
    tsplit_kernel<<<dim3(QKV_N / 32, KDIM / 32), 256>>>(Wv, WvTh, WvTl, KDIM, QKV_N);
    tsplit_kernel<<<dim3(DMODEL / 32, KDIM / 32), 256>>>(Wo, WoTh, WoTl, KDIM, DMODEL);

    // projections (mma.sync bf16x3, cp.async pipelined)
    gemm_mma<<<dim3(QKV_N / 128, T_SEQ / 128), 256, gemm_smem>>>(Xh, Xl, WqTh, WqTl, bq, Q, QKV_N);
    gemm_mma<<<dim3(DMODEL / 128, T_SEQ / 128), 256, gemm_smem>>>(Xh, Xl, WkTh, WkTl, bk, K, DMODEL);
    gemm_mma<<<dim3(QKV_N / 128, T_SEQ / 128), 256, gemm_smem>>>(Xh, Xl, WvTh, WvTl, bv, V, QKV_N);

    rope_table_kernel<<<(T_SEQ * 32 + 255) / 256, 256>>>();
    kscale_kernel<<<(NHEAD * T_SEQ * 32 + 255) / 256, 256>>>();

    attn_kernel<<<dim3(16, HTOT), 128, attn_smem>>>(sink, vnull);

    avg_kernel<<<(T_SEQ * (DMODEL / 4) + 255) / 256, 256>>>();
    // reuse Xh/Xl for the context split (X split is dead after projections)
    esplit_kernel<<<T_SEQ * KDIM / 4 / 256, 256>>>(CA, Xh, Xl, T_SEQ * KDIM);
    gemm_mma<<<dim3(DMODEL / 128, T_SEQ / 128), 256, gemm_smem>>>(Xh, Xl, WoTh, WoTl, bo, out, DMODEL);
}

// round 13
// speedup vs baseline: 1.6232x; 1.1157x over previous
#include <cuda_runtime.h>
#include <cuda_bf16.h>
#include <cstdint>
#include <math.h>

#define T_SEQ   1024
#define DMODEL  1024
#define NHEAD   16
#define HTOT    64
#define DH      64
#define QKV_N   (HTOT*DH)   /* 4096 */
#define KDIM    1024
#define ATTN_SCALE 0.125f
#define SIGM_SCALE 1.8137993642342178f   /* pi/sqrt(3) */

// ---------------- scratch (device globals; no allocation allowed) -------------
__device__ float  g_Q[T_SEQ*QKV_N];
__device__ float  g_K[T_SEQ*DMODEL];
__device__ float  g_V[T_SEQ*QKV_N];
__device__ float  g_kscale[NHEAD*T_SEQ];
__device__ float2 g_rope[T_SEQ*32];
__device__ float  g_ctx[T_SEQ*QKV_N];
__device__ float  g_ctxavg[T_SEQ*DMODEL];

// bf16 hi/lo split operands (g_Xh/g_Xl reused for the context split after attn)
__device__ __nv_bfloat16 g_Xh[T_SEQ*KDIM],    g_Xl[T_SEQ*KDIM];
__device__ __nv_bfloat16 g_WqTh[QKV_N*KDIM],  g_WqTl[QKV_N*KDIM];
__device__ __nv_bfloat16 g_WkTh[DMODEL*KDIM], g_WkTl[DMODEL*KDIM];
__device__ __nv_bfloat16 g_WvTh[QKV_N*KDIM],  g_WvTl[QKV_N*KDIM];
__device__ __nv_bfloat16 g_WoTh[DMODEL*KDIM], g_WoTl[DMODEL*KDIM];

// ---------------- PTX helpers --------------------------------------------------
__device__ __forceinline__ unsigned smem_u32(const void* p) {
    return (unsigned)__cvta_generic_to_shared(p);
}
__device__ __forceinline__ void ldsm_x4(unsigned* r, unsigned a) {
    asm volatile("ldmatrix.sync.aligned.m8n8.x4.shared.b16 {%0,%1,%2,%3}, [%4];"
        : "=r"(r[0]), "=r"(r[1]), "=r"(r[2]), "=r"(r[3]) : "r"(a));
}
__device__ __forceinline__ void mma_bf16(float* c, const unsigned* a,
                                         unsigned b0, unsigned b1) {
    asm volatile("mma.sync.aligned.m16n8k16.row.col.f32.bf16.bf16.f32 "
        "{%0,%1,%2,%3},{%4,%5,%6,%7},{%8,%9},{%0,%1,%2,%3};"
        : "+f"(c[0]), "+f"(c[1]), "+f"(c[2]), "+f"(c[3])
        : "r"(a[0]), "r"(a[1]), "r"(a[2]), "r"(a[3]), "r"(b0), "r"(b1));
}
__device__ __forceinline__ void cp16(unsigned dst, const void* src) {
    asm volatile("cp.async.cg.shared.global [%0], [%1], 16;"
        :: "r"(dst), "l"(src) : "memory");
}
__device__ __forceinline__ void cp_commit() {
    asm volatile("cp.async.commit_group;" ::: "memory");
}
// packed fp32x2 (exact fp32 semantics, 2 MACs / instruction)
__device__ __forceinline__ unsigned long long pack2(float lo, float hi) {
    unsigned long long r;
    asm("mov.b64 %0, {%1, %2};" : "=l"(r) : "f"(lo), "f"(hi));
    return r;
}
__device__ __forceinline__ void fma2(unsigned long long& d,
                                     unsigned long long a, unsigned long long b) {
    asm("fma.rn.f32x2 %0, %1, %2, %0;" : "+l"(d) : "l"(a), "l"(b));
}
__device__ __forceinline__ void unpack2(unsigned long long v, float& lo, float& hi) {
    asm("mov.b64 {%0, %1}, %2;" : "=f"(lo), "=f"(hi) : "l"(v));
}

// ---------------- split kernels -------------------------------------------------
__global__ void esplit_kernel(const float* __restrict__ A,
                              __nv_bfloat16* __restrict__ H,
                              __nv_bfloat16* __restrict__ L, int n)
{
    int i = (blockIdx.x * blockDim.x + threadIdx.x) * 4;
    if (i >= n) return;
    float4 v = *(const float4*)(A + i);
    __nv_bfloat16 hx = __float2bfloat16(v.x);
    __nv_bfloat16 hy = __float2bfloat16(v.y);
    __nv_bfloat16 hz = __float2bfloat16(v.z);
    __nv_bfloat16 hw = __float2bfloat16(v.w);
    H[i + 0] = hx; H[i + 1] = hy; H[i + 2] = hz; H[i + 3] = hw;
    L[i + 0] = __float2bfloat16(v.x - __bfloat162float(hx));
    L[i + 1] = __float2bfloat16(v.y - __bfloat162float(hy));
    L[i + 2] = __float2bfloat16(v.z - __bfloat162float(hz));
    L[i + 3] = __float2bfloat16(v.w - __bfloat162float(hw));
}

// transpose + split: W[K][N] fp32 -> Th/Tl [N][K] bf16
__global__ __launch_bounds__(256)
void tsplit_kernel(const float* __restrict__ W,
                   __nv_bfloat16* __restrict__ Th,
                   __nv_bfloat16* __restrict__ Tl, int K, int N)
{
    __shared__ float t[32][33];
    const int tid = threadIdx.x;
    const int tx = tid & 31, ty = tid >> 5;
    const int k0 = blockIdx.y * 32, n0 = blockIdx.x * 32;
    #pragma unroll
    for (int r = 0; r < 4; r++) {
        int k = k0 + ty + r * 8;
        t[ty + r * 8][tx] = W[(size_t)k * N + n0 + tx];
    }
    __syncthreads();
    #pragma unroll
    for (int r = 0; r < 4; r++) {
        int n = n0 + ty + r * 8;
        int k = k0 + tx;
        float v = t[tx][ty + r * 8];
        __nv_bfloat16 h = __float2bfloat16(v);
        Th[(size_t)n * K + k] = h;
        Tl[(size_t)n * K + k] = __float2bfloat16(v - __bfloat162float(h));
    }
}

// ---------------- mma.sync GEMM: C = Ahl @ Bhl^T + bias ------------------------
#define TILE_B  8192                 /* 128 rows x 64B */
#define STG_B   (4*TILE_B)           /* Ah, Al, Bh, Bl  */
__global__ __launch_bounds__(256)
void gemm_mma(const __nv_bfloat16* __restrict__ Ah, const __nv_bfloat16* __restrict__ Al,
              const __nv_bfloat16* __restrict__ Bh, const __nv_bfloat16* __restrict__ Bl,
              const float* __restrict__ bias, float* __restrict__ C, int N)
{
    extern __shared__ char smem[];
    const int tid  = threadIdx.x;
    const int lane = tid & 31;
    const int warp = tid >> 5;
    const int wm   = warp & 1;
    const int wn   = warp >> 1;
    const int rowBase = blockIdx.y * 128;
    const int colBase = blockIdx.x * 128;
    const __nv_bfloat16* srcs[4] = { Ah, Al, Bh, Bl };

    auto load_stage = [&](int ch, int stg) {
        char* sp = smem + stg * STG_B;
        #pragma unroll
        for (int i = 0; i < 8; i++) {
            int idx = tid + i * 256;
            int t   = idx >> 9;
            int rem = idx & 511;
            int row = rem >> 2;
            int c   = rem & 3;
            int gr  = (t < 2 ? rowBase : colBase) + row;
            const __nv_bfloat16* g = srcs[t] + (size_t)gr * KDIM + ch * 32 + c * 8;
            unsigned dst = smem_u32(sp + t * TILE_B + row * 64 +
                                    ((c ^ ((row >> 1) & 3)) * 16));
            cp16(dst, g);
        }
        cp_commit();
    };

    float acc[4][4][4] = {};
    const int NCH = KDIM / 32;   // 32

    load_stage(0, 0);
    for (int ch = 0; ch < NCH; ch++) {
        const int stg = ch & 1;
        if (ch + 1 < NCH) {
            load_stage(ch + 1, stg ^ 1);
            asm volatile("cp.async.wait_group 1;" ::: "memory");
        } else {
            asm volatile("cp.async.wait_group 0;" ::: "memory");
        }
        __syncthreads();

        char* sp = smem + stg * STG_B;
        #pragma unroll
        for (int ks = 0; ks < 2; ks++) {
            unsigned aH[4][4], aL[4][4], bH[2][4], bL[2][4];
            const int half  = lane >> 4;
            const int chunk = ks * 2 + half;
            #pragma unroll
            for (int ms = 0; ms < 4; ms++) {
                int row = wm * 64 + (lane & 15) + ms * 16;
                unsigned off = row * 64 + ((chunk ^ ((row >> 1) & 3)) * 16);
                ldsm_x4(aH[ms], smem_u32(sp + off));
                ldsm_x4(aL[ms], smem_u32(sp + TILE_B + off));
            }
            #pragma unroll
            for (int np = 0; np < 2; np++) {
                int row = wn * 32 + (lane & 15) + np * 16;
                unsigned off = row * 64 + ((chunk ^ ((row >> 1) & 3)) * 16);
                ldsm_x4(bH[np], smem_u32(sp + 2 * TILE_B + off));
                ldsm_x4(bL[np], smem_u32(sp + 3 * TILE_B + off));
            }
            #pragma unroll
            for (int ms = 0; ms < 4; ms++) {
                #pragma unroll
                for (int bg = 0; bg < 4; bg++) {
                    const int np = bg >> 1, gg = bg & 1;
                    mma_bf16(acc[ms][bg], aH[ms], bH[np][gg], bH[np][gg + 2]);
                    mma_bf16(acc[ms][bg], aH[ms], bL[np][gg], bL[np][gg + 2]);
                    mma_bf16(acc[ms][bg], aL[ms], bH[np][gg], bH[np][gg + 2]);
                }
            }
        }
        __syncthreads();
    }

    #pragma unroll
    for (int ms = 0; ms < 4; ms++) {
        int r0 = rowBase + wm * 64 + ms * 16 + (lane >> 2);
        #pragma unroll
        for (int bg = 0; bg < 4; bg++) {
            int col = colBase + wn * 32 + (bg >> 1) * 16 + (bg & 1) * 8 + (lane & 3) * 2;
            float2 bv = *(const float2*)(bias + col);
            float2 o0, o1;
            o0.x = acc[ms][bg][0] + bv.x;
            o0.y = acc[ms][bg][1] + bv.y;
            o1.x = acc[ms][bg][2] + bv.x;
            o1.y = acc[ms][bg][3] + bv.y;
            *(float2*)(C + (size_t)r0 * N + col)       = o0;
            *(float2*)(C + (size_t)(r0 + 8) * N + col) = o1;
        }
    }
}

// ---------------- RoPE cos/sin table ------------------------------------------
__global__ void rope_table_kernel()
{
    int idx = blockIdx.x * blockDim.x + threadIdx.x;
    if (idx >= T_SEQ * 32) return;
    int t = idx >> 5;
    int p = idx & 31;
    float inv = expf(-(float)p * 0.28782313662425575f);
    float ang = (float)t * inv;
    float s, c;
    sincosf(ang, &s, &c);
    g_rope[idx] = make_float2(c, s);
}

// ---------------- key norm scale (rope preserves |k|^2) ------------------------
__global__ void kscale_kernel()
{
    int gw   = (blockIdx.x * blockDim.x + threadIdx.x) >> 5;
    int lane = threadIdx.x & 31;
    if (gw >= NHEAD * T_SEQ) return;
    int hb = gw >> 10;
    int t  = gw & 1023;
    const float* kp = g_K + (size_t)t * DMODEL + hb * DH;
    float2 v = *(const float2*)(kp + 2 * lane);
    float s = v.x * v.x + v.y * v.y;
    #pragma unroll
    for (int o = 16; o; o >>= 1) s += __shfl_xor_sync(0xffffffffu, s, o);
    if (lane == 0)
        g_kscale[hb * T_SEQ + t] = ATTN_SCALE / sqrtf(fmaxf(s, 1e-6f));
}

// ---------------- attention: block = (128 queries, 1 head), 128 threads --------
// Thread tile 8x8, packed f32x2 FMA (2 MAC/instr). Key tiles of 64.
// Smem: Qt[d][i] roped Q^T (64x132), KW = roped K^T (64x64) then W^T (64x128,
// XOR-swizzled cols), Vs[s][d'] (64x68).
#define QT_STRIDE 132
#define VS_STRIDE 68
__global__ __launch_bounds__(128)
void attn_kernel(const float* __restrict__ sink_sc,
                 const float* __restrict__ v_nulls)
{
    extern __shared__ float sm[];
    float* Qt = sm;                         // [64][132]
    float* KW = sm + 64 * QT_STRIDE;        // [64][132]
    float* Vs = sm + 2 * 64 * QT_STRIDE;    // [64][68]

    const int qi  = blockIdx.x;             // 0..7 (128-query tiles)
    const int h   = blockIdx.y;             // 0..63
    const int hb  = h & 15;
    const int tid = threadIdx.x;
    const int tx  = tid & 7;                // 8 key-col groups
    const int ty  = tid >> 3;               // 16 query-row groups
    const int t0  = qi * 128;
    const int i0  = ty * 8;
    const int j0  = tx * 8;

    // ---- load + rope + transpose Q tile (128 x 64) ----
    #pragma unroll
    for (int r = 0; r < 16; r++) {
        int idx = tid + r * 128;
        int i   = idx >> 4;
        int d4  = idx & 15;
        int t   = t0 + i;
        float4 v  = *(const float4*)(g_Q + (size_t)t * QKV_N + h * DH + d4 * 4);
        float2 c0 = g_rope[t * 32 + 2 * d4];
        float2 c1 = g_rope[t * 32 + 2 * d4 + 1];
        Qt[(2 * d4)      * QT_STRIDE + i] = v.x * c0.x - v.y * c0.y;
        Qt[(2 * d4 + 1)  * QT_STRIDE + i] = v.z * c1.x - v.w * c1.y;
        Qt[(2 * d4 + 32) * QT_STRIDE + i] = v.x * c0.y + v.y * c0.x;
        Qt[(2 * d4 + 33) * QT_STRIDE + i] = v.z * c1.y + v.w * c1.x;
    }

    unsigned long long acc2[8][4] = {};
    float rowsum[8] = {};
    const int nkt = 2 * qi + 2;

    for (int kt = 0; kt < nkt; kt++) {
        const int s0 = kt * 64;
        __syncthreads();

        // ---- load + rope K^T, load V (64 x 64 each) ----
        #pragma unroll
        for (int r = 0; r < 8; r++) {
            int idx = tid + r * 128;
            int j   = idx >> 4;
            int d4  = idx & 15;
            int s   = s0 + j;
            float4 kv = *(const float4*)(g_K + (size_t)s * DMODEL + hb * DH + d4 * 4);
            float2 c0 = g_rope[s * 32 + 2 * d4];
            float2 c1 = g_rope[s * 32 + 2 * d4 + 1];
            KW[(2 * d4)      * QT_STRIDE + j] = kv.x * c0.x - kv.y * c0.y;
            KW[(2 * d4 + 1)  * QT_STRIDE + j] = kv.z * c1.x - kv.w * c1.y;
            KW[(2 * d4 + 32) * QT_STRIDE + j] = kv.x * c0.y + kv.y * c0.x;
            KW[(2 * d4 + 33) * QT_STRIDE + j] = kv.z * c1.y + kv.w * c1.x;
            *(float4*)&Vs[j * VS_STRIDE + d4 * 4] =
                *(const float4*)(g_V + (size_t)s * QKV_N + h * DH + d4 * 4);
        }
        __syncthreads();

        // ---- S = Q K^T : 8x8 per thread (packed f32x2) ----
        unsigned long long sreg2[8][4] = {};
        #pragma unroll
        for (int d = 0; d < 64; d++) {
            float4 a0 = *(float4*)&Qt[d * QT_STRIDE + i0];
            float4 a1 = *(float4*)&Qt[d * QT_STRIDE + i0 + 4];
            ulonglong2 p01 = *(ulonglong2*)&KW[d * QT_STRIDE + j0];
            ulonglong2 p23 = *(ulonglong2*)&KW[d * QT_STRIDE + j0 + 4];
            unsigned long long b2[4] = { p01.x, p01.y, p23.x, p23.y };
            float av[8] = { a0.x, a0.y, a0.z, a0.w, a1.x, a1.y, a1.z, a1.w };
            #pragma unroll
            for (int ii = 0; ii < 8; ii++) {
                unsigned long long a2 = pack2(av[ii], av[ii]);
                #pragma unroll
                for (int p = 0; p < 4; p++) fma2(sreg2[ii][p], a2, b2[p]);
            }
        }
        __syncthreads();   // all K^T reads done; KW will be overwritten with W^T

        // ---- activation + causal mask ----
        float ksc[8];
        *(float4*)&ksc[0] = *(const float4*)(g_kscale + hb * T_SEQ + s0 + j0);
        *(float4*)&ksc[4] = *(const float4*)(g_kscale + hb * T_SEQ + s0 + j0 + 4);
        const bool diag = (kt >= 2 * qi);
        float wv[8][8];   // [jj][ii]
        #pragma unroll
        for (int ii = 0; ii < 8; ii++) {
            int tg = t0 + i0 + ii;
            #pragma unroll
            for (int p = 0; p < 4; p++) {
                float x0, x1;
                unpack2(sreg2[ii][p], x0, x1);
                {
                    float x  = x0 * ksc[2 * p];
                    float sp = (x > 15.f) ? x : __logf(1.f + __expf(x));
                    float w  = __fdividef(sp, 1.f + __expf(-SIGM_SCALE * sp));
                    if (diag && (s0 + j0 + 2 * p > tg)) w = 0.f;
                    rowsum[ii] += w;
                    wv[2 * p][ii] = w;
                }
                {
                    float x  = x1 * ksc[2 * p + 1];
                    float sp = (x > 15.f) ? x : __logf(1.f + __expf(x));
                    float w  = __fdividef(sp, 1.f + __expf(-SIGM_SCALE * sp));
                    if (diag && (s0 + j0 + 2 * p + 1 > tg)) w = 0.f;
                    rowsum[ii] += w;
                    wv[2 * p + 1][ii] = w;
                }
            }
        }

        // ---- store W^T (rows j, cols i) with XOR swizzle ----
        #pragma unroll
        for (int jj = 0; jj < 8; jj++) {
            int j = j0 + jj;
            unsigned swz = (unsigned)tx << 2;
            float4 f0 = make_float4(wv[jj][0], wv[jj][1], wv[jj][2], wv[jj][3]);
            float4 f1 = make_float4(wv[jj][4], wv[jj][5], wv[jj][6], wv[jj][7]);
            *(float4*)&KW[j * QT_STRIDE + (((unsigned)i0)     ^ swz)] = f0;
            *(float4*)&KW[j * QT_STRIDE + (((unsigned)i0 + 4) ^ swz)] = f1;
        }
        __syncthreads();

        // ---- acc += W V : 8x8 per thread (packed f32x2) ----
        #pragma unroll
        for (int s = 0; s < 64; s++) {
            unsigned swzs = (unsigned)((s >> 3) & 7) << 2;
            float4 a0 = *(float4*)&KW[s * QT_STRIDE + (((unsigned)i0)     ^ swzs)];
            float4 a1 = *(float4*)&KW[s * QT_STRIDE + (((unsigned)i0 + 4) ^ swzs)];
            ulonglong2 p01 = *(ulonglong2*)&Vs[s * VS_STRIDE + j0];
            ulonglong2 p23 = *(ulonglong2*)&Vs[s * VS_STRIDE + j0 + 4];
            unsigned long long b2[4] = { p01.x, p01.y, p23.x, p23.y };
            float av[8] = { a0.x, a0.y, a0.z, a0.w, a1.x, a1.y, a1.z, a1.w };
            #pragma unroll
            for (int ii = 0; ii < 8; ii++) {
                unsigned long long a2 = pack2(av[ii], av[ii]);
                #pragma unroll
                for (int p = 0; p < 4; p++) fma2(acc2[ii][p], a2, b2[p]);
            }
        }
    }

    // rowsum reduce across the 8 tx lanes (lane bits 0..2)
    #pragma unroll
    for (int o = 1; o < 8; o <<= 1)
        #pragma unroll
        for (int ii = 0; ii < 8; ii++)
            rowsum[ii] += __shfl_xor_sync(0xffffffffu, rowsum[ii], o);

    float sink = tanhf(sink_sc[h]) + 1e-6f;
    float vn[8];
    *(float4*)&vn[0] = *(const float4*)(v_nulls + h * DH + j0);
    *(float4*)&vn[4] = *(const float4*)(v_nulls + h * DH + j0 + 4);
    #pragma unroll
    for (int ii = 0; ii < 8; ii++) {
        float alpha = __fdividef(1.f, rowsum[ii] + sink + 1e-6f);
        int t = t0 + i0 + ii;
        float o[8];
        #pragma unroll
        for (int p = 0; p < 4; p++) unpack2(acc2[ii][p], o[2 * p], o[2 * p + 1]);
        float4 o0, o1;
        o0.x = (o[0] + sink * vn[0]) * alpha;
        o0.y = (o[1] + sink * vn[1]) * alpha;
        o0.z = (o[2] + sink * vn[2]) * alpha;
        o0.w = (o[3] + sink * vn[3]) * alpha;
        o1.x = (o[4] + sink * vn[4]) * alpha;
        o1.y = (o[5] + sink * vn[5]) * alpha;
        o1.z = (o[6] + sink * vn[6]) * alpha;
        o1.w = (o[7] + sink * vn[7]) * alpha;
        *(float4*)(g_ctx + (size_t)t * QKV_N + h * DH + j0)     = o0;
        *(float4*)(g_ctx + (size_t)t * QKV_N + h * DH + j0 + 4) = o1;
    }
}

// ---------------- average the 4 branches --------------------------------------
__global__ void avg_kernel()
{
    int idx = blockIdx.x * blockDim.x + threadIdx.x;
    if (idx >= T_SEQ * (DMODEL / 4)) return;
    int t   = idx >> 8;
    int c   = (idx & 255) << 2;
    int h16 = c >> 6;
    int d   = c & 63;
    float4 r = make_float4(0.f, 0.f, 0.f, 0.f);
    #pragma unroll
    for (int br = 0; br < 4; br++) {
        float4 v = *(const float4*)(g_ctx + (size_t)t * QKV_N + (br * 16 + h16) * DH + d);
        r.x += v.x; r.y += v.y; r.z += v.z; r.w += v.w;
    }
    r.x *= 0.25f; r.y *= 0.25f; r.z *= 0.25f; r.w *= 0.25f;
    *(float4*)(g_ctxavg + (size_t)t * DMODEL + c) = r;
}

// ---------------- launch -------------------------------------------------------
extern "C" void kernel_launch(void* const* d_in, const int* in_sizes, int n_in,
                              void* d_out, int out_size)
{
    const float* X     = (const float*)d_in[0];
    const float* Wq    = (const float*)d_in[1];
    const float* bq    = (const float*)d_in[2];
    const float* Wk    = (const float*)d_in[3];
    const float* bk    = (const float*)d_in[4];
    const float* Wv    = (const float*)d_in[5];
    const float* bv    = (const float*)d_in[6];
    const float* sink  = (const float*)d_in[7];
    const float* vnull = (const float*)d_in[8];
    const float* Wo    = (const float*)d_in[9];
    const float* bo    = (const float*)d_in[10];
    float* out         = (float*)d_out;

    float *Q, *K, *V, *CA;
    cudaGetSymbolAddress((void**)&Q,  g_Q);
    cudaGetSymbolAddress((void**)&K,  g_K);
    cudaGetSymbolAddress((void**)&V,  g_V);
    cudaGetSymbolAddress((void**)&CA, g_ctxavg);
    __nv_bfloat16 *Xh, *Xl, *WqTh, *WqTl, *WkTh, *WkTl, *WvTh, *WvTl, *WoTh, *WoTl;
    cudaGetSymbolAddress((void**)&Xh,   g_Xh);
    cudaGetSymbolAddress((void**)&Xl,   g_Xl);
    cudaGetSymbolAddress((void**)&WqTh, g_WqTh);
    cudaGetSymbolAddress((void**)&WqTl, g_WqTl);
    cudaGetSymbolAddress((void**)&WkTh, g_WkTh);
    cudaGetSymbolAddress((void**)&WkTl, g_WkTl);
    cudaGetSymbolAddress((void**)&WvTh, g_WvTh);
    cudaGetSymbolAddress((void**)&WvTl, g_WvTl);
    cudaGetSymbolAddress((void**)&WoTh, g_WoTh);
    cudaGetSymbolAddress((void**)&WoTl, g_WoTl);

    const int attn_smem = (2 * 64 * QT_STRIDE + 64 * VS_STRIDE) * sizeof(float); // 84992
    cudaFuncSetAttribute(attn_kernel,
                         cudaFuncAttributeMaxDynamicSharedMemorySize, attn_smem);
    const int gemm_smem = 2 * STG_B;                            // 65536
    cudaFuncSetAttribute(gemm_mma,
                         cudaFuncAttributeMaxDynamicSharedMemorySize, gemm_smem);

    // launch order puts gemm_mma at profiled slot (index 3)
    rope_table_kernel<<<(T_SEQ * 32 + 255) / 256, 256>>>();
    esplit_kernel<<<T_SEQ * KDIM / 4 / 256, 256>>>(X, Xh, Xl, T_SEQ * KDIM);
    tsplit_kernel<<<dim3(QKV_N / 32, KDIM / 32), 256>>>(Wq, WqTh, WqTl, KDIM, QKV_N);
    gemm_mma<<<dim3(QKV_N / 128, T_SEQ / 128), 256, gemm_smem>>>(Xh, Xl, WqTh, WqTl, bq, Q, QKV_N);
    tsplit_kernel<<<dim3(DMODEL / 32, KDIM / 32), 256>>>(Wk, WkTh, WkTl, KDIM, DMODEL);
    gemm_mma<<<dim3(DMODEL / 128, T_SEQ / 128), 256, gemm_smem>>>(Xh, Xl, WkTh, WkTl, bk, K, DMODEL);
    tsplit_kernel<<<dim3(QKV_N / 32, KDIM / 32), 256>>>(Wv, WvTh, WvTl, KDIM, QKV_N);
    gemm_mma<<<dim3(QKV_N / 128, T_SEQ / 128), 256, gemm_smem>>>(Xh, Xl, WvTh, WvTl, bv, V, QKV_N);
    tsplit_kernel<<<dim3(DMODEL / 32, KDIM / 32), 256>>>(Wo, WoTh, WoTl, KDIM, DMODEL);

    kscale_kernel<<<(NHEAD * T_SEQ * 32 + 255) / 256, 256>>>();

    attn_kernel<<<dim3(8, HTOT), 128, attn_smem>>>(sink, vnull);

    avg_kernel<<<(T_SEQ * (DMODEL / 4) + 255) / 256, 256>>>();
    esplit_kernel<<<T_SEQ * KDIM / 4 / 256, 256>>>(CA, Xh, Xl, T_SEQ * KDIM);
    gemm_mma<<<dim3(DMODEL / 128, T_SEQ / 128), 256, gemm_smem>>>(Xh, Xl, WoTh, WoTl, bo, out, DMODEL);
}

// round 15
// speedup vs baseline: 1.7396x; 1.0718x over previous
#include <cuda_runtime.h>
#include <cuda_bf16.h>
#include <cstdint>
#include <math.h>

#define T_SEQ   1024
#define DMODEL  1024
#define NHEAD   16
#define HTOT    64
#define DH      64
#define KDIM    1024
#define NQKV    9216            /* 4096 Q + 1024 K + 4096 V */
#define QOFF    0
#define KOFF    4096
#define VOFF    5120
#define ATTN_SCALE 0.125f
#define SIGM_SCALE 1.8137993642342178f   /* pi/sqrt(3) */

// ---------------- scratch (device globals; no allocation allowed) -------------
__device__ float  g_QKV[T_SEQ*NQKV];       // fused projection output
__device__ float  g_kscale[NHEAD*T_SEQ];
__device__ float2 g_rope[T_SEQ*32];
__device__ float  g_ctx[T_SEQ*HTOT*DH];
__device__ float  g_ctxavg[T_SEQ*DMODEL];
__device__ float  g_bqkv[NQKV];

__device__ __nv_bfloat16 g_Xh[T_SEQ*KDIM],     g_Xl[T_SEQ*KDIM];
__device__ __nv_bfloat16 g_WqkvTh[NQKV*KDIM],  g_WqkvTl[NQKV*KDIM];
__device__ __nv_bfloat16 g_WoTh[DMODEL*KDIM],  g_WoTl[DMODEL*KDIM];

// ---------------- PTX helpers --------------------------------------------------
__device__ __forceinline__ unsigned smem_u32(const void* p) {
    return (unsigned)__cvta_generic_to_shared(p);
}
__device__ __forceinline__ void ldsm_x4(unsigned* r, unsigned a) {
    asm volatile("ldmatrix.sync.aligned.m8n8.x4.shared.b16 {%0,%1,%2,%3}, [%4];"
        : "=r"(r[0]), "=r"(r[1]), "=r"(r[2]), "=r"(r[3]) : "r"(a));
}
__device__ __forceinline__ void mma_bf16(float* c, const unsigned* a,
                                         unsigned b0, unsigned b1) {
    asm volatile("mma.sync.aligned.m16n8k16.row.col.f32.bf16.bf16.f32 "
        "{%0,%1,%2,%3},{%4,%5,%6,%7},{%8,%9},{%0,%1,%2,%3};"
        : "+f"(c[0]), "+f"(c[1]), "+f"(c[2]), "+f"(c[3])
        : "r"(a[0]), "r"(a[1]), "r"(a[2]), "r"(a[3]), "r"(b0), "r"(b1));
}
__device__ __forceinline__ void cp16(unsigned dst, const void* src) {
    asm volatile("cp.async.cg.shared.global [%0], [%1], 16;"
        :: "r"(dst), "l"(src) : "memory");
}
__device__ __forceinline__ void cp_commit() {
    asm volatile("cp.async.commit_group;" ::: "memory");
}
// packed fp32x2 (exact fp32 semantics, 2 MACs / instruction)
__device__ __forceinline__ unsigned long long pack2(float lo, float hi) {
    unsigned long long r;
    asm("mov.b64 %0, {%1, %2};" : "=l"(r) : "f"(lo), "f"(hi));
    return r;
}
__device__ __forceinline__ void fma2(unsigned long long& d,
                                     unsigned long long a, unsigned long long b) {
    asm("fma.rn.f32x2 %0, %1, %2, %0;" : "+l"(d) : "l"(a), "l"(b));
}
__device__ __forceinline__ void unpack2(unsigned long long v, float& lo, float& hi) {
    asm("mov.b64 {%0, %1}, %2;" : "=f"(lo), "=f"(hi) : "l"(v));
}

// ---------------- bias concat ---------------------------------------------------
__global__ void bcat_kernel(const float* __restrict__ bq, const float* __restrict__ bk,
                            const float* __restrict__ bv)
{
    int i = blockIdx.x * blockDim.x + threadIdx.x;
    if (i >= NQKV) return;
    float v;
    if (i < KOFF)      v = bq[i];
    else if (i < VOFF) v = bk[i - KOFF];
    else               v = bv[i - VOFF];
    g_bqkv[i] = v;
}

// ---------------- split kernels -------------------------------------------------
__global__ void esplit_kernel(const float* __restrict__ A,
                              __nv_bfloat16* __restrict__ H,
                              __nv_bfloat16* __restrict__ L, int n)
{
    int i = (blockIdx.x * blockDim.x + threadIdx.x) * 4;
    if (i >= n) return;
    float4 v = *(const float4*)(A + i);
    __nv_bfloat16 hx = __float2bfloat16(v.x);
    __nv_bfloat16 hy = __float2bfloat16(v.y);
    __nv_bfloat16 hz = __float2bfloat16(v.z);
    __nv_bfloat16 hw = __float2bfloat16(v.w);
    H[i + 0] = hx; H[i + 1] = hy; H[i + 2] = hz; H[i + 3] = hw;
    L[i + 0] = __float2bfloat16(v.x - __bfloat162float(hx));
    L[i + 1] = __float2bfloat16(v.y - __bfloat162float(hy));
    L[i + 2] = __float2bfloat16(v.z - __bfloat162float(hz));
    L[i + 3] = __float2bfloat16(v.w - __bfloat162float(hw));
}

// transpose + split generic: W[K][N] fp32 -> Th/Tl rows [rowOff+n][K] bf16
__device__ __forceinline__ void tsplit_body(const float* W, __nv_bfloat16* Th,
                                            __nv_bfloat16* Tl, int N, int n0,
                                            int k0, int rowOff, int tid)
{
    __shared__ float t[32][33];
    const int tx = tid & 31, ty = tid >> 5;
    #pragma unroll
    for (int r = 0; r < 4; r++) {
        int k = k0 + ty + r * 8;
        t[ty + r * 8][tx] = W[(size_t)k * N + n0 + tx];
    }
    __syncthreads();
    #pragma unroll
    for (int r = 0; r < 4; r++) {
        int n = n0 + ty + r * 8;
        int k = k0 + tx;
        float v = t[tx][ty + r * 8];
        __nv_bfloat16 h = __float2bfloat16(v);
        Th[(size_t)(rowOff + n) * KDIM + k] = h;
        Tl[(size_t)(rowOff + n) * KDIM + k] = __float2bfloat16(v - __bfloat162float(h));
    }
}

__global__ __launch_bounds__(256)
void tsplit_qkv_kernel(const float* __restrict__ Wq, const float* __restrict__ Wk,
                       const float* __restrict__ Wv)
{
    int n0 = blockIdx.x * 32;           // global row in [0, 9216)
    int k0 = blockIdx.y * 32;
    const float* W; int N; int loc;
    if (n0 < KOFF)      { W = Wq; N = 4096; loc = n0; }
    else if (n0 < VOFF) { W = Wk; N = 1024; loc = n0 - KOFF; }
    else                { W = Wv; N = 4096; loc = n0 - VOFF; }
    tsplit_body(W, g_WqkvTh, g_WqkvTl, N, loc, k0, n0 - loc, threadIdx.x);
}

__global__ __launch_bounds__(256)
void tsplit_wo_kernel(const float* __restrict__ Wo)
{
    tsplit_body(Wo, g_WoTh, g_WoTl, DMODEL, blockIdx.x * 32, blockIdx.y * 32,
                0, threadIdx.x);
}

// ---------------- mma.sync GEMM: C = Ahl @ Bhl^T + bias ------------------------
#define TILE_B  8192                 /* 128 rows x 64B */
#define STG_B   (4*TILE_B)           /* Ah, Al, Bh, Bl  */
__global__ __launch_bounds__(256)
void gemm_mma(const __nv_bfloat16* __restrict__ Ah, const __nv_bfloat16* __restrict__ Al,
              const __nv_bfloat16* __restrict__ Bh, const __nv_bfloat16* __restrict__ Bl,
              const float* __restrict__ bias, float* __restrict__ C, int N)
{
    extern __shared__ char smem[];
    const int tid  = threadIdx.x;
    const int lane = tid & 31;
    const int warp = tid >> 5;
    const int wm   = warp & 1;
    const int wn   = warp >> 1;
    const int rowBase = blockIdx.y * 128;
    const int colBase = blockIdx.x * 128;
    const __nv_bfloat16* srcs[4] = { Ah, Al, Bh, Bl };

    auto load_stage = [&](int ch, int stg) {
        char* sp = smem + stg * STG_B;
        #pragma unroll
        for (int i = 0; i < 8; i++) {
            int idx = tid + i * 256;
            int t   = idx >> 9;
            int rem = idx & 511;
            int row = rem >> 2;
            int c   = rem & 3;
            int gr  = (t < 2 ? rowBase : colBase) + row;
            const __nv_bfloat16* g = srcs[t] + (size_t)gr * KDIM + ch * 32 + c * 8;
            unsigned dst = smem_u32(sp + t * TILE_B + row * 64 +
                                    ((c ^ ((row >> 1) & 3)) * 16));
            cp16(dst, g);
        }
        cp_commit();
    };

    float acc[4][4][4] = {};
    const int NCH = KDIM / 32;   // 32

    load_stage(0, 0);
    for (int ch = 0; ch < NCH; ch++) {
        const int stg = ch & 1;
        if (ch + 1 < NCH) {
            load_stage(ch + 1, stg ^ 1);
            asm volatile("cp.async.wait_group 1;" ::: "memory");
        } else {
            asm volatile("cp.async.wait_group 0;" ::: "memory");
        }
        __syncthreads();

        char* sp = smem + stg * STG_B;
        #pragma unroll
        for (int ks = 0; ks < 2; ks++) {
            unsigned aH[4][4], aL[4][4], bH[2][4], bL[2][4];
            const int half  = lane >> 4;
            const int chunk = ks * 2 + half;
            #pragma unroll
            for (int ms = 0; ms < 4; ms++) {
                int row = wm * 64 + (lane & 15) + ms * 16;
                unsigned off = row * 64 + ((chunk ^ ((row >> 1) & 3)) * 16);
                ldsm_x4(aH[ms], smem_u32(sp + off));
                ldsm_x4(aL[ms], smem_u32(sp + TILE_B + off));
            }
            #pragma unroll
            for (int np = 0; np < 2; np++) {
                int row = wn * 32 + (lane & 15) + np * 16;
                unsigned off = row * 64 + ((chunk ^ ((row >> 1) & 3)) * 16);
                ldsm_x4(bH[np], smem_u32(sp + 2 * TILE_B + off));
                ldsm_x4(bL[np], smem_u32(sp + 3 * TILE_B + off));
            }
            #pragma unroll
            for (int ms = 0; ms < 4; ms++) {
                #pragma unroll
                for (int bg = 0; bg < 4; bg++) {
                    const int np = bg >> 1, gg = bg & 1;
                    mma_bf16(acc[ms][bg], aH[ms], bH[np][gg], bH[np][gg + 2]);
                    mma_bf16(acc[ms][bg], aH[ms], bL[np][gg], bL[np][gg + 2]);
                    mma_bf16(acc[ms][bg], aL[ms], bH[np][gg], bH[np][gg + 2]);
                }
            }
        }
        __syncthreads();
    }

    #pragma unroll
    for (int ms = 0; ms < 4; ms++) {
        int r0 = rowBase + wm * 64 + ms * 16 + (lane >> 2);
        #pragma unroll
        for (int bg = 0; bg < 4; bg++) {
            int col = colBase + wn * 32 + (bg >> 1) * 16 + (bg & 1) * 8 + (lane & 3) * 2;
            float2 bv = *(const float2*)(bias + col);
            float2 o0, o1;
            o0.x = acc[ms][bg][0] + bv.x;
            o0.y = acc[ms][bg][1] + bv.y;
            o1.x = acc[ms][bg][2] + bv.x;
            o1.y = acc[ms][bg][3] + bv.y;
            *(float2*)(C + (size_t)r0 * N + col)       = o0;
            *(float2*)(C + (size_t)(r0 + 8) * N + col) = o1;
        }
    }
}

// ---------------- RoPE cos/sin table ------------------------------------------
__global__ void rope_table_kernel()
{
    int idx = blockIdx.x * blockDim.x + threadIdx.x;
    if (idx >= T_SEQ * 32) return;
    int t = idx >> 5;
    int p = idx & 31;
    float inv = expf(-(float)p * 0.28782313662425575f);
    float ang = (float)t * inv;
    float s, c;
    sincosf(ang, &s, &c);
    g_rope[idx] = make_float2(c, s);
}

// ---------------- key norm scale (rope preserves |k|^2) ------------------------
__global__ void kscale_kernel()
{
    int gw   = (blockIdx.x * blockDim.x + threadIdx.x) >> 5;
    int lane = threadIdx.x & 31;
    if (gw >= NHEAD * T_SEQ) return;
    int hb = gw >> 10;
    int t  = gw & 1023;
    const float* kp = g_QKV + (size_t)t * NQKV + KOFF + hb * DH;
    float2 v = *(const float2*)(kp + 2 * lane);
    float s = v.x * v.x + v.y * v.y;
    #pragma unroll
    for (int o = 16; o; o >>= 1) s += __shfl_xor_sync(0xffffffffu, s, o);
    if (lane == 0)
        g_kscale[hb * T_SEQ + t] = ATTN_SCALE / sqrtf(fmaxf(s, 1e-6f));
}

// ---------------- attention ----------------------------------------------------
// Block = (128 queries, 1 head), 128 threads. Thread: kg = tid&7, qg = tid>>3.
// S^T computed directly (K broadcast x Q^T packed): no transpose staging regs.
// W^T stored swizzled; WV phase reads W^T rows, V as strided d-pairs.
#define QT_STRIDE 132
#define VS_STRIDE 68
__global__ __launch_bounds__(128)
void attn_kernel(const float* __restrict__ sink_sc,
                 const float* __restrict__ v_nulls)
{
    extern __shared__ float sm[];
    float* Qt = sm;                         // [64 d][132] Q^T, i < 128
    float* KW = sm + 64 * QT_STRIDE;        // [64 d][j<64] K^T -> [64 s][i] W^T
    float* Vs = sm + 2 * 64 * QT_STRIDE;    // [64 s][68]

    const int qi  = blockIdx.x;             // 0..7
    const int h   = blockIdx.y;             // 0..63
    const int hb  = h & 15;
    const int tid = threadIdx.x;
    const int kg  = tid & 7;                // key group (8 rows)
    const int qg  = tid >> 3;               // query group (8 cols)
    const int t0  = qi * 128;
    const int i0  = qg * 8;
    const int j0  = kg * 8;

    // ---- load + rope + transpose Q tile (128 x 64) ----
    #pragma unroll
    for (int r = 0; r < 16; r++) {
        int idx = tid + r * 128;
        int i   = idx >> 4;
        int d4  = idx & 15;
        int t   = t0 + i;
        float4 v  = *(const float4*)(g_QKV + (size_t)t * NQKV + QOFF + h * DH + d4 * 4);
        float2 c0 = g_rope[t * 32 + 2 * d4];
        float2 c1 = g_rope[t * 32 + 2 * d4 + 1];
        Qt[(2 * d4)      * QT_STRIDE + i] = v.x * c0.x - v.y * c0.y;
        Qt[(2 * d4 + 1)  * QT_STRIDE + i] = v.z * c1.x - v.w * c1.y;
        Qt[(2 * d4 + 32) * QT_STRIDE + i] = v.x * c0.y + v.y * c0.x;
        Qt[(2 * d4 + 33) * QT_STRIDE + i] = v.z * c1.y + v.w * c1.x;
    }

    unsigned long long acc2[8][4] = {};     // [ii][p]: i = i0+ii, d = 2*kg+16*p
    float rsum[8] = {};                     // per query col i0+ii (partial over kg)
    const int nkt = 2 * qi + 2;

    for (int kt = 0; kt < nkt; kt++) {
        const int s0 = kt * 64;
        __syncthreads();

        // ---- load + rope K^T, load V (64 x 64 each) ----
        #pragma unroll
        for (int r = 0; r < 8; r++) {
            int idx = tid + r * 128;
            int j   = idx >> 4;
            int d4  = idx & 15;
            int s   = s0 + j;
            float4 kv = *(const float4*)(g_QKV + (size_t)s * NQKV + KOFF + hb * DH + d4 * 4);
            float2 c0 = g_rope[s * 32 + 2 * d4];
            float2 c1 = g_rope[s * 32 + 2 * d4 + 1];
            KW[(2 * d4)      * QT_STRIDE + j] = kv.x * c0.x - kv.y * c0.y;
            KW[(2 * d4 + 1)  * QT_STRIDE + j] = kv.z * c1.x - kv.w * c1.y;
            KW[(2 * d4 + 32) * QT_STRIDE + j] = kv.x * c0.y + kv.y * c0.x;
            KW[(2 * d4 + 33) * QT_STRIDE + j] = kv.z * c1.y + kv.w * c1.x;
            *(float4*)&Vs[j * VS_STRIDE + d4 * 4] =
                *(const float4*)(g_QKV + (size_t)s * NQKV + VOFF + h * DH + d4 * 4);
        }
        __syncthreads();

        // ---- S^T = (K Q^T): 8 key-rows x 8 query-cols per thread, packed ----
        unsigned long long sregT2[8][4] = {};
        #pragma unroll
        for (int d = 0; d < 64; d++) {
            float4 k0 = *(float4*)&KW[d * QT_STRIDE + j0];
            float4 k1 = *(float4*)&KW[d * QT_STRIDE + j0 + 4];
            ulonglong2 q01 = *(ulonglong2*)&Qt[d * QT_STRIDE + i0];
            ulonglong2 q23 = *(ulonglong2*)&Qt[d * QT_STRIDE + i0 + 4];
            unsigned long long b2[4] = { q01.x, q01.y, q23.x, q23.y };
            float kv[8] = { k0.x, k0.y, k0.z, k0.w, k1.x, k1.y, k1.z, k1.w };
            #pragma unroll
            for (int jj = 0; jj < 8; jj++) {
                unsigned long long a2 = pack2(kv[jj], kv[jj]);
                #pragma unroll
                for (int p = 0; p < 4; p++) fma2(sregT2[jj][p], a2, b2[p]);
            }
        }
        __syncthreads();   // K^T reads done; KW becomes W^T

        // ---- activation + mask; store W^T rows directly ----
        float kscv[8];
        *(float4*)&kscv[0] = *(const float4*)(g_kscale + hb * T_SEQ + s0 + j0);
        *(float4*)&kscv[4] = *(const float4*)(g_kscale + hb * T_SEQ + s0 + j0 + 4);
        const bool diag = (kt >= 2 * qi);
        #pragma unroll
        for (int jj = 0; jj < 8; jj++) {
            const int jglob = s0 + j0 + jj;
            const float kk  = kscv[jj];
            float wrow[8];
            #pragma unroll
            for (int p = 0; p < 4; p++) {
                float x0, x1;
                unpack2(sregT2[jj][p], x0, x1);
                float xa = x0 * kk;
                float sa = (xa > 15.f) ? xa : __logf(1.f + __expf(xa));
                float w0 = __fdividef(sa, 1.f + __expf(-SIGM_SCALE * sa));
                if (diag && (jglob > t0 + i0 + 2 * p)) w0 = 0.f;
                float xb = x1 * kk;
                float sb = (xb > 15.f) ? xb : __logf(1.f + __expf(xb));
                float w1 = __fdividef(sb, 1.f + __expf(-SIGM_SCALE * sb));
                if (diag && (jglob > t0 + i0 + 2 * p + 1)) w1 = 0.f;
                rsum[2 * p]     += w0;
                rsum[2 * p + 1] += w1;
                wrow[2 * p]     = w0;
                wrow[2 * p + 1] = w1;
            }
            const int row = j0 + jj;
            const unsigned swz = (unsigned)kg << 2;    // row>>3 == kg
            *(float4*)&KW[row * QT_STRIDE + (((unsigned)i0)     ^ swz)] =
                make_float4(wrow[0], wrow[1], wrow[2], wrow[3]);
            *(float4*)&KW[row * QT_STRIDE + (((unsigned)i0 + 4) ^ swz)] =
                make_float4(wrow[4], wrow[5], wrow[6], wrow[7]);
        }
        __syncthreads();

        // ---- acc += W V : 8 query-rows x 8 d-cols (d strided pairs) ----
        #pragma unroll
        for (int s = 0; s < 64; s++) {
            const unsigned swz = (unsigned)((s >> 3) & 7) << 2;
            float4 a0 = *(float4*)&KW[s * QT_STRIDE + (((unsigned)i0)     ^ swz)];
            float4 a1 = *(float4*)&KW[s * QT_STRIDE + (((unsigned)i0 + 4) ^ swz)];
            unsigned long long b2[4];
            #pragma unroll
            for (int p = 0; p < 4; p++)
                b2[p] = *(unsigned long long*)&Vs[s * VS_STRIDE + 2 * kg + 16 * p];
            float av[8] = { a0.x, a0.y, a0.z, a0.w, a1.x, a1.y, a1.z, a1.w };
            #pragma unroll
            for (int ii = 0; ii < 8; ii++) {
                unsigned long long a2 = pack2(av[ii], av[ii]);
                #pragma unroll
                for (int p = 0; p < 4; p++) fma2(acc2[ii][p], a2, b2[p]);
            }
        }
    }

    // reduce rsum across the 8 kg lanes (lane bits 0..2)
    #pragma unroll
    for (int o = 1; o < 8; o <<= 1)
        #pragma unroll
        for (int ii = 0; ii < 8; ii++)
            rsum[ii] += __shfl_xor_sync(0xffffffffu, rsum[ii], o);

    const float sink = tanhf(sink_sc[h]) + 1e-6f;
    float2 vn[4];
    #pragma unroll
    for (int p = 0; p < 4; p++)
        vn[p] = *(const float2*)(v_nulls + h * DH + 2 * kg + 16 * p);

    #pragma unroll
    for (int ii = 0; ii < 8; ii++) {
        const float alpha = __fdividef(1.f, rsum[ii] + sink + 1e-6f);
        const int t = t0 + i0 + ii;
        #pragma unroll
        for (int p = 0; p < 4; p++) {
            float o0, o1;
            unpack2(acc2[ii][p], o0, o1);
            float2 st;
            st.x = (o0 + sink * vn[p].x) * alpha;
            st.y = (o1 + sink * vn[p].y) * alpha;
            *(float2*)(g_ctx + (size_t)t * (HTOT * DH) + h * DH + 2 * kg + 16 * p) = st;
        }
    }
}

// ---------------- average the 4 branches --------------------------------------
__global__ void avg_kernel()
{
    int idx = blockIdx.x * blockDim.x + threadIdx.x;
    if (idx >= T_SEQ * (DMODEL / 4)) return;
    int t   = idx >> 8;
    int c   = (idx & 255) << 2;
    int h16 = c >> 6;
    int d   = c & 63;
    float4 r = make_float4(0.f, 0.f, 0.f, 0.f);
    #pragma unroll
    for (int br = 0; br < 4; br++) {
        float4 v = *(const float4*)(g_ctx + (size_t)t * (HTOT * DH) +
                                    (br * 16 + h16) * DH + d);
        r.x += v.x; r.y += v.y; r.z += v.z; r.w += v.w;
    }
    r.x *= 0.25f; r.y *= 0.25f; r.z *= 0.25f; r.w *= 0.25f;
    *(float4*)(g_ctxavg + (size_t)t * DMODEL + c) = r;
}

// ---------------- launch -------------------------------------------------------
extern "C" void kernel_launch(void* const* d_in, const int* in_sizes, int n_in,
                              void* d_out, int out_size)
{
    const float* X     = (const float*)d_in[0];
    const float* Wq    = (const float*)d_in[1];
    const float* bq    = (const float*)d_in[2];
    const float* Wk    = (const float*)d_in[3];
    const float* bk    = (const float*)d_in[4];
    const float* Wv    = (const float*)d_in[5];
    const float* bv    = (const float*)d_in[6];
    const float* sink  = (const float*)d_in[7];
    const float* vnull = (const float*)d_in[8];
    const float* Wo    = (const float*)d_in[9];
    const float* bo    = (const float*)d_in[10];
    float* out         = (float*)d_out;

    float *QKV, *CA, *BQKV;
    cudaGetSymbolAddress((void**)&QKV,  g_QKV);
    cudaGetSymbolAddress((void**)&CA,   g_ctxavg);
    cudaGetSymbolAddress((void**)&BQKV, g_bqkv);
    __nv_bfloat16 *Xh, *Xl, *WqkvTh, *WqkvTl, *WoTh, *WoTl;
    cudaGetSymbolAddress((void**)&Xh,     g_Xh);
    cudaGetSymbolAddress((void**)&Xl,     g_Xl);
    cudaGetSymbolAddress((void**)&WqkvTh, g_WqkvTh);
    cudaGetSymbolAddress((void**)&WqkvTl, g_WqkvTl);
    cudaGetSymbolAddress((void**)&WoTh,   g_WoTh);
    cudaGetSymbolAddress((void**)&WoTl,   g_WoTl);

    const int attn_smem = (2 * 64 * QT_STRIDE + 64 * VS_STRIDE) * sizeof(float); // 84992
    cudaFuncSetAttribute(attn_kernel,
                         cudaFuncAttributeMaxDynamicSharedMemorySize, attn_smem);
    const int gemm_smem = 2 * STG_B;                            // 65536
    cudaFuncSetAttribute(gemm_mma,
                         cudaFuncAttributeMaxDynamicSharedMemorySize, gemm_smem);

    // 0: bias concat   1: X split   2: fused weight transpose+split
    bcat_kernel<<<(NQKV + 255) / 256, 256>>>(bq, bk, bv);
    esplit_kernel<<<T_SEQ * KDIM / 4 / 256, 256>>>(X, Xh, Xl, T_SEQ * KDIM);
    tsplit_qkv_kernel<<<dim3(NQKV / 32, KDIM / 32), 256>>>(Wq, Wk, Wv);

    // 3: fused QKV projection (profiled slot)
    gemm_mma<<<dim3(NQKV / 128, T_SEQ / 128), 256, gemm_smem>>>(
        Xh, Xl, WqkvTh, WqkvTl, BQKV, QKV, NQKV);

    // 4..6: Wo prep + rope + kscale
    tsplit_wo_kernel<<<dim3(DMODEL / 32, KDIM / 32), 256>>>(Wo);
    rope_table_kernel<<<(T_SEQ * 32 + 255) / 256, 256>>>();
    kscale_kernel<<<(NHEAD * T_SEQ * 32 + 255) / 256, 256>>>();

    // 7: attention
    attn_kernel<<<dim3(8, HTOT), 128, attn_smem>>>(sink, vnull);

    // 8..10: branch average + output projection
    avg_kernel<<<(T_SEQ * (DMODEL / 4) + 255) / 256, 256>>>();
    esplit_kernel<<<T_SEQ * KDIM / 4 / 256, 256>>>(CA, Xh, Xl, T_SEQ * KDIM);
    gemm_mma<<<dim3(DMODEL / 128, T_SEQ / 128), 256, gemm_smem>>>(
        Xh, Xl, WoTh, WoTl, bo, out, DMODEL);
}

// round 16
// speedup vs baseline: 2.4231x; 1.3929x over previous
#include <cuda_runtime.h>
#include <cuda_bf16.h>
#include <cstdint>
#include <math.h>

#define T_SEQ   1024
#define DMODEL  1024
#define NHEAD   16
#define HTOT    64
#define DH      64
#define KDIM    1024
#define NQKV    9216            /* 4096 Q + 1024 K + 4096 V */
#define QOFF    0
#define KOFF    4096
#define VOFF    5120
#define ATTN_SCALE 0.125f
#define SIGM_SCALE 1.8137993642342178f   /* pi/sqrt(3) */

// ---------------- scratch (device globals; no allocation allowed) -------------
__device__ float  g_QKV[T_SEQ*NQKV];
__device__ float  g_kscale[NHEAD*T_SEQ];
__device__ float2 g_rope[T_SEQ*32];
__device__ float  g_ctx[T_SEQ*HTOT*DH];
__device__ float  g_ctxavg[T_SEQ*DMODEL];
__device__ float  g_bqkv[NQKV];

__device__ __nv_bfloat16 g_Xh[T_SEQ*KDIM],     g_Xl[T_SEQ*KDIM];
__device__ __nv_bfloat16 g_WqkvTh[NQKV*KDIM],  g_WqkvTl[NQKV*KDIM];
__device__ __nv_bfloat16 g_WoTh[DMODEL*KDIM],  g_WoTl[DMODEL*KDIM];

// bf16 hi/lo attention operands
__device__ __nv_bfloat16 g_Qbh[HTOT*T_SEQ*DH],  g_Qbl[HTOT*T_SEQ*DH];   // [h][t][d] roped
__device__ __nv_bfloat16 g_Kbh[NHEAD*T_SEQ*DH], g_Kbl[NHEAD*T_SEQ*DH];  // [hb][t][d] roped
__device__ __nv_bfloat16 g_VTh[HTOT*DH*T_SEQ],  g_VTl[HTOT*DH*T_SEQ];   // [h*64+d][t]

// ---------------- PTX helpers --------------------------------------------------
__device__ __forceinline__ unsigned smem_u32(const void* p) {
    return (unsigned)__cvta_generic_to_shared(p);
}
__device__ __forceinline__ void ldsm_x4(unsigned* r, unsigned a) {
    asm volatile("ldmatrix.sync.aligned.m8n8.x4.shared.b16 {%0,%1,%2,%3}, [%4];"
        : "=r"(r[0]), "=r"(r[1]), "=r"(r[2]), "=r"(r[3]) : "r"(a));
}
__device__ __forceinline__ void mma_bf16(float* c, const unsigned* a,
                                         unsigned b0, unsigned b1) {
    asm volatile("mma.sync.aligned.m16n8k16.row.col.f32.bf16.bf16.f32 "
        "{%0,%1,%2,%3},{%4,%5,%6,%7},{%8,%9},{%0,%1,%2,%3};"
        : "+f"(c[0]), "+f"(c[1]), "+f"(c[2]), "+f"(c[3])
        : "r"(a[0]), "r"(a[1]), "r"(a[2]), "r"(a[3]), "r"(b0), "r"(b1));
}
__device__ __forceinline__ void cp16(unsigned dst, const void* src) {
    asm volatile("cp.async.cg.shared.global [%0], [%1], 16;"
        :: "r"(dst), "l"(src) : "memory");
}
__device__ __forceinline__ void cp_commit() {
    asm volatile("cp.async.commit_group;" ::: "memory");
}

// ---------------- bias concat ---------------------------------------------------
__global__ void bcat_kernel(const float* __restrict__ bq, const float* __restrict__ bk,
                            const float* __restrict__ bv)
{
    int i = blockIdx.x * blockDim.x + threadIdx.x;
    if (i >= NQKV) return;
    float v;
    if (i < KOFF)      v = bq[i];
    else if (i < VOFF) v = bk[i - KOFF];
    else               v = bv[i - VOFF];
    g_bqkv[i] = v;
}

// ---------------- split kernels -------------------------------------------------
__global__ void esplit_kernel(const float* __restrict__ A,
                              __nv_bfloat16* __restrict__ H,
                              __nv_bfloat16* __restrict__ L, int n)
{
    int i = (blockIdx.x * blockDim.x + threadIdx.x) * 4;
    if (i >= n) return;
    float4 v = *(const float4*)(A + i);
    __nv_bfloat16 hx = __float2bfloat16(v.x);
    __nv_bfloat16 hy = __float2bfloat16(v.y);
    __nv_bfloat16 hz = __float2bfloat16(v.z);
    __nv_bfloat16 hw = __float2bfloat16(v.w);
    H[i + 0] = hx; H[i + 1] = hy; H[i + 2] = hz; H[i + 3] = hw;
    L[i + 0] = __float2bfloat16(v.x - __bfloat162float(hx));
    L[i + 1] = __float2bfloat16(v.y - __bfloat162float(hy));
    L[i + 2] = __float2bfloat16(v.z - __bfloat162float(hz));
    L[i + 3] = __float2bfloat16(v.w - __bfloat162float(hw));
}

__device__ __forceinline__ void tsplit_body(const float* W, __nv_bfloat16* Th,
                                            __nv_bfloat16* Tl, int N, int n0,
                                            int k0, int rowOff, int tid)
{
    __shared__ float t[32][33];
    const int tx = tid & 31, ty = tid >> 5;
    #pragma unroll
    for (int r = 0; r < 4; r++) {
        int k = k0 + ty + r * 8;
        t[ty + r * 8][tx] = W[(size_t)k * N + n0 + tx];
    }
    __syncthreads();
    #pragma unroll
    for (int r = 0; r < 4; r++) {
        int n = n0 + ty + r * 8;
        int k = k0 + tx;
        float v = t[tx][ty + r * 8];
        __nv_bfloat16 h = __float2bfloat16(v);
        Th[(size_t)(rowOff + n) * KDIM + k] = h;
        Tl[(size_t)(rowOff + n) * KDIM + k] = __float2bfloat16(v - __bfloat162float(h));
    }
}

__global__ __launch_bounds__(256)
void tsplit_qkv_kernel(const float* __restrict__ Wq, const float* __restrict__ Wk,
                       const float* __restrict__ Wv)
{
    int n0 = blockIdx.x * 32;
    int k0 = blockIdx.y * 32;
    const float* W; int N; int loc;
    if (n0 < KOFF)      { W = Wq; N = 4096; loc = n0; }
    else if (n0 < VOFF) { W = Wk; N = 1024; loc = n0 - KOFF; }
    else                { W = Wv; N = 4096; loc = n0 - VOFF; }
    tsplit_body(W, g_WqkvTh, g_WqkvTl, N, loc, k0, n0 - loc, threadIdx.x);
}

__global__ __launch_bounds__(256)
void tsplit_wo_kernel(const float* __restrict__ Wo)
{
    tsplit_body(Wo, g_WoTh, g_WoTl, DMODEL, blockIdx.x * 32, blockIdx.y * 32,
                0, threadIdx.x);
}

// ---------------- mma.sync GEMM: C = Ahl @ Bhl^T + bias ------------------------
#define TILE_B  8192
#define STG_B   (4*TILE_B)
__global__ __launch_bounds__(256)
void gemm_mma(const __nv_bfloat16* __restrict__ Ah, const __nv_bfloat16* __restrict__ Al,
              const __nv_bfloat16* __restrict__ Bh, const __nv_bfloat16* __restrict__ Bl,
              const float* __restrict__ bias, float* __restrict__ C, int N)
{
    extern __shared__ char smem[];
    const int tid  = threadIdx.x;
    const int lane = tid & 31;
    const int warp = tid >> 5;
    const int wm   = warp & 1;
    const int wn   = warp >> 1;
    const int rowBase = blockIdx.y * 128;
    const int colBase = blockIdx.x * 128;
    const __nv_bfloat16* srcs[4] = { Ah, Al, Bh, Bl };

    auto load_stage = [&](int ch, int stg) {
        char* sp = smem + stg * STG_B;
        #pragma unroll
        for (int i = 0; i < 8; i++) {
            int idx = tid + i * 256;
            int t   = idx >> 9;
            int rem = idx & 511;
            int row = rem >> 2;
            int c   = rem & 3;
            int gr  = (t < 2 ? rowBase : colBase) + row;
            const __nv_bfloat16* g = srcs[t] + (size_t)gr * KDIM + ch * 32 + c * 8;
            unsigned dst = smem_u32(sp + t * TILE_B + row * 64 +
                                    ((c ^ ((row >> 1) & 3)) * 16));
            cp16(dst, g);
        }
        cp_commit();
    };

    float acc[4][4][4] = {};
    const int NCH = KDIM / 32;

    load_stage(0, 0);
    for (int ch = 0; ch < NCH; ch++) {
        const int stg = ch & 1;
        if (ch + 1 < NCH) {
            load_stage(ch + 1, stg ^ 1);
            asm volatile("cp.async.wait_group 1;" ::: "memory");
        } else {
            asm volatile("cp.async.wait_group 0;" ::: "memory");
        }
        __syncthreads();

        char* sp = smem + stg * STG_B;
        #pragma unroll
        for (int ks = 0; ks < 2; ks++) {
            unsigned aH[4][4], aL[4][4], bH[2][4], bL[2][4];
            const int half  = lane >> 4;
            const int chunk = ks * 2 + half;
            #pragma unroll
            for (int ms = 0; ms < 4; ms++) {
                int row = wm * 64 + (lane & 15) + ms * 16;
                unsigned off = row * 64 + ((chunk ^ ((row >> 1) & 3)) * 16);
                ldsm_x4(aH[ms], smem_u32(sp + off));
                ldsm_x4(aL[ms], smem_u32(sp + TILE_B + off));
            }
            #pragma unroll
            for (int np = 0; np < 2; np++) {
                int row = wn * 32 + (lane & 15) + np * 16;
                unsigned off = row * 64 + ((chunk ^ ((row >> 1) & 3)) * 16);
                ldsm_x4(bH[np], smem_u32(sp + 2 * TILE_B + off));
                ldsm_x4(bL[np], smem_u32(sp + 3 * TILE_B + off));
            }
            #pragma unroll
            for (int ms = 0; ms < 4; ms++) {
                #pragma unroll
                for (int bg = 0; bg < 4; bg++) {
                    const int np = bg >> 1, gg = bg & 1;
                    mma_bf16(acc[ms][bg], aH[ms], bH[np][gg], bH[np][gg + 2]);
                    mma_bf16(acc[ms][bg], aH[ms], bL[np][gg], bL[np][gg + 2]);
                    mma_bf16(acc[ms][bg], aL[ms], bH[np][gg], bH[np][gg + 2]);
                }
            }
        }
        __syncthreads();
    }

    #pragma unroll
    for (int ms = 0; ms < 4; ms++) {
        int r0 = rowBase + wm * 64 + ms * 16 + (lane >> 2);
        #pragma unroll
        for (int bg = 0; bg < 4; bg++) {
            int col = colBase + wn * 32 + (bg >> 1) * 16 + (bg & 1) * 8 + (lane & 3) * 2;
            float2 bv = *(const float2*)(bias + col);
            float2 o0, o1;
            o0.x = acc[ms][bg][0] + bv.x;
            o0.y = acc[ms][bg][1] + bv.y;
            o1.x = acc[ms][bg][2] + bv.x;
            o1.y = acc[ms][bg][3] + bv.y;
            *(float2*)(C + (size_t)r0 * N + col)       = o0;
            *(float2*)(C + (size_t)(r0 + 8) * N + col) = o1;
        }
    }
}

// ---------------- RoPE cos/sin table ------------------------------------------
__global__ void rope_table_kernel()
{
    int idx = blockIdx.x * blockDim.x + threadIdx.x;
    if (idx >= T_SEQ * 32) return;
    int t = idx >> 5;
    int p = idx & 31;
    float inv = expf(-(float)p * 0.28782313662425575f);
    float ang = (float)t * inv;
    float s, c;
    sincosf(ang, &s, &c);
    g_rope[idx] = make_float2(c, s);
}

// ---------------- rope + bf16 split of Q (64 heads) and K (16 heads) ------------
__global__ void ropesplit_kernel()
{
    int idx = blockIdx.x * blockDim.x + threadIdx.x;
    if (idx >= 80 * T_SEQ * 32) return;
    int p = idx & 31;
    int t = (idx >> 5) & 1023;
    int u = idx >> 15;                       // 0..63 Q, 64..79 K
    const float* src;
    __nv_bfloat16 *dh, *dl;
    size_t base;
    if (u < 64) {
        src = g_QKV + (size_t)t * NQKV + QOFF + u * 64;
        base = ((size_t)u * T_SEQ + t) * 64;
        dh = g_Qbh; dl = g_Qbl;
    } else {
        int ub = u - 64;
        src = g_QKV + (size_t)t * NQKV + KOFF + ub * 64;
        base = ((size_t)ub * T_SEQ + t) * 64;
        dh = g_Kbh; dl = g_Kbl;
    }
    float x0 = src[2 * p];
    float x1 = src[2 * p + 1];
    float2 cs = g_rope[t * 32 + p];
    float o0 = x0 * cs.x - x1 * cs.y;
    float o1 = x0 * cs.y + x1 * cs.x;
    __nv_bfloat16 h0 = __float2bfloat16(o0);
    __nv_bfloat16 h1 = __float2bfloat16(o1);
    dh[base + p]      = h0;
    dh[base + 32 + p] = h1;
    dl[base + p]      = __float2bfloat16(o0 - __bfloat162float(h0));
    dl[base + 32 + p] = __float2bfloat16(o1 - __bfloat162float(h1));
}

// ---------------- V transpose + split: [t][c] -> VT[c][t] bf16 hi/lo ------------
__global__ __launch_bounds__(256)
void vtsplit_kernel()
{
    __shared__ float t[32][33];
    const int tid = threadIdx.x;
    const int tx = tid & 31, ty = tid >> 5;
    const int c0 = blockIdx.x * 32;          // channel (h*64+d)
    const int t0 = blockIdx.y * 32;          // time
    #pragma unroll
    for (int r = 0; r < 4; r++) {
        int tt = t0 + ty + r * 8;
        t[ty + r * 8][tx] = g_QKV[(size_t)tt * NQKV + VOFF + c0 + tx];
    }
    __syncthreads();
    #pragma unroll
    for (int r = 0; r < 4; r++) {
        int c  = c0 + ty + r * 8;
        int tt = t0 + tx;
        float v = t[tx][ty + r * 8];
        __nv_bfloat16 h = __float2bfloat16(v);
        g_VTh[(size_t)c * T_SEQ + tt] = h;
        g_VTl[(size_t)c * T_SEQ + tt] = __float2bfloat16(v - __bfloat162float(h));
    }
}

// ---------------- key norm scale (rope preserves |k|^2) ------------------------
__global__ void kscale_kernel()
{
    int gw   = (blockIdx.x * blockDim.x + threadIdx.x) >> 5;
    int lane = threadIdx.x & 31;
    if (gw >= NHEAD * T_SEQ) return;
    int hb = gw >> 10;
    int t  = gw & 1023;
    const float* kp = g_QKV + (size_t)t * NQKV + KOFF + hb * DH;
    float2 v = *(const float2*)(kp + 2 * lane);
    float s = v.x * v.x + v.y * v.y;
    #pragma unroll
    for (int o = 16; o; o >>= 1) s += __shfl_xor_sync(0xffffffffu, s, o);
    if (lane == 0)
        g_kscale[hb * T_SEQ + t] = ATTN_SCALE / sqrtf(fmaxf(s, 1e-6f));
}

// ---------------- tensor-core attention ----------------------------------------
// CTA = 128 queries x 1 head; 8 warps (16 q-rows each). bf16x3 MMAs.
// smem: Qh(16K) Ql(16K) + 2 stages x {Kh,Kl,Vh,Vl}(8K each) = 96KB.
#define AS_Q   0
#define AS_STG 32768
__global__ __launch_bounds__(256)
void attn_mma_kernel(const float* __restrict__ sink_sc,
                     const float* __restrict__ v_nulls)
{
    extern __shared__ char sm[];
    const int qi   = blockIdx.x;            // 0..7
    const int h    = blockIdx.y;            // 0..63
    const int hb   = h & 15;
    const int tid  = threadIdx.x;
    const int lane = tid & 31;
    const int warp = tid >> 5;
    const int t0   = qi * 128;
    const int nkt  = 2 * qi + 2;

    // ---- prologue loads: Q hi/lo tiles + KV tile 0 ----
    {
        #pragma unroll
        for (int i = 0; i < 8; i++) {
            int idx = tid + i * 256;
            int tl  = idx >> 10;
            int rem = idx & 1023;
            int row = rem >> 3;
            int c   = rem & 7;
            const __nv_bfloat16* g = (tl ? g_Qbl : g_Qbh) +
                ((size_t)h * T_SEQ + t0 + row) * 64 + c * 8;
            cp16(smem_u32(sm + AS_Q + tl * 16384 + row * 128 + ((c ^ (row & 7)) * 16)), g);
        }
        cp_commit();
    }

    auto load_kv = [&](int kt, int stg) {
        char* sp = sm + AS_STG + stg * 32768;
        int s0 = kt * 64;
        #pragma unroll
        for (int i = 0; i < 8; i++) {
            int idx = tid + i * 256;
            int t4  = idx >> 9;
            int rem = idx & 511;
            int row = rem >> 3;
            int c   = rem & 7;
            const __nv_bfloat16* g;
            if (t4 == 0)
                g = g_Kbh + ((size_t)hb * T_SEQ + s0 + row) * 64 + c * 8;
            else if (t4 == 1)
                g = g_Kbl + ((size_t)hb * T_SEQ + s0 + row) * 64 + c * 8;
            else if (t4 == 2)
                g = g_VTh + ((size_t)(h * 64 + row)) * T_SEQ + s0 + c * 8;
            else
                g = g_VTl + ((size_t)(h * 64 + row)) * T_SEQ + s0 + c * 8;
            cp16(smem_u32(sp + t4 * 8192 + row * 128 + ((c ^ (row & 7)) * 16)), g);
        }
        cp_commit();
    };

    load_kv(0, 0);
    asm volatile("cp.async.wait_group 0;" ::: "memory");
    __syncthreads();

    // ---- Q fragments (persistent) ----
    unsigned qh[4][4], ql[4][4];
    #pragma unroll
    for (int ks = 0; ks < 4; ks++) {
        int row   = (warp << 4) + (lane & 15);
        int chunk = ks * 2 + (lane >> 4);
        unsigned off = row * 128 + ((chunk ^ (row & 7)) * 16);
        ldsm_x4(qh[ks], smem_u32(sm + AS_Q + off));
        ldsm_x4(ql[ks], smem_u32(sm + AS_Q + 16384 + off));
    }

    float acc[8][4] = {};
    float rsum0 = 0.f, rsum1 = 0.f;
    const int r0g = t0 + (warp << 4) + (lane >> 2);
    const int r1g = r0g + 8;

    for (int kt = 0; kt < nkt; kt++) {
        const int stg = kt & 1;
        const int s0  = kt * 64;
        if (kt + 1 < nkt) {
            load_kv(kt + 1, stg ^ 1);
            asm volatile("cp.async.wait_group 1;" ::: "memory");
        } else {
            asm volatile("cp.async.wait_group 0;" ::: "memory");
        }
        __syncthreads();

        char* sp = sm + AS_STG + stg * 32768;

        // ---- S = Q K^T (bf16x3) ----
        float S[8][4] = {};
        #pragma unroll
        for (int ks = 0; ks < 4; ks++) {
            #pragma unroll
            for (int ng = 0; ng < 4; ng++) {
                int row   = ng * 16 + (lane & 15);
                int chunk = ks * 2 + (lane >> 4);
                unsigned off = row * 128 + ((chunk ^ (row & 7)) * 16);
                unsigned bh[4], bl[4];
                ldsm_x4(bh, smem_u32(sp + off));
                ldsm_x4(bl, smem_u32(sp + 8192 + off));
                #pragma unroll
                for (int sub = 0; sub < 2; sub++) {
                    float* s = S[ng * 2 + sub];
                    mma_bf16(s, qh[ks], bh[sub], bh[sub + 2]);
                    mma_bf16(s, qh[ks], bl[sub], bl[sub + 2]);
                    mma_bf16(s, ql[ks], bh[sub], bh[sub + 2]);
                }
            }
        }

        // ---- activation; W packed directly as A-fragments (hi/lo) ----
        unsigned Wh[4][4], Wl[4][4];
        const bool diag = (s0 + 63) > (t0 + (warp << 4));
        #pragma unroll
        for (int j = 0; j < 8; j++) {
            float2 ks2 = *(const float2*)(g_kscale + hb * T_SEQ + s0 + 8 * j + 2 * (lane & 3));
            float w[4];
            #pragma unroll
            for (int e = 0; e < 4; e++) {
                float x  = S[j][e] * ((e & 1) ? ks2.y : ks2.x);
                float sp2 = (x > 15.f) ? x : __logf(1.f + __expf(x));
                w[e] = __fdividef(sp2, 1.f + __expf(-SIGM_SCALE * sp2));
            }
            if (diag) {
                int k0g = s0 + 8 * j + 2 * (lane & 3);
                if (k0g     > r0g) w[0] = 0.f;
                if (k0g + 1 > r0g) w[1] = 0.f;
                if (k0g     > r1g) w[2] = 0.f;
                if (k0g + 1 > r1g) w[3] = 0.f;
            }
            rsum0 += w[0] + w[1];
            rsum1 += w[2] + w[3];
            __nv_bfloat16 h0 = __float2bfloat16(w[0]);
            __nv_bfloat16 h1 = __float2bfloat16(w[1]);
            __nv_bfloat16 h2 = __float2bfloat16(w[2]);
            __nv_bfloat16 h3 = __float2bfloat16(w[3]);
            __nv_bfloat162 hh01 = __halves2bfloat162(h0, h1);
            __nv_bfloat162 hh23 = __halves2bfloat162(h2, h3);
            __nv_bfloat162 ll01 = __halves2bfloat162(
                __float2bfloat16(w[0] - __bfloat162float(h0)),
                __float2bfloat16(w[1] - __bfloat162float(h1)));
            __nv_bfloat162 ll23 = __halves2bfloat162(
                __float2bfloat16(w[2] - __bfloat162float(h2)),
                __float2bfloat16(w[3] - __bfloat162float(h3)));
            int kk  = j >> 1;
            int off = (j & 1) * 2;
            Wh[kk][off]     = *(unsigned*)&hh01;
            Wh[kk][off + 1] = *(unsigned*)&hh23;
            Wl[kk][off]     = *(unsigned*)&ll01;
            Wl[kk][off + 1] = *(unsigned*)&ll23;
        }

        // ---- acc += W V (bf16x3), V^T via pre-transposed layout ----
        #pragma unroll
        for (int kk = 0; kk < 4; kk++) {
            #pragma unroll
            for (int ng = 0; ng < 4; ng++) {
                int row   = ng * 16 + (lane & 15);
                int chunk = kk * 2 + (lane >> 4);
                unsigned off = row * 128 + ((chunk ^ (row & 7)) * 16);
                unsigned bh[4], bl[4];
                ldsm_x4(bh, smem_u32(sp + 16384 + off));
                ldsm_x4(bl, smem_u32(sp + 24576 + off));
                #pragma unroll
                for (int sub = 0; sub < 2; sub++) {
                    float* a = acc[ng * 2 + sub];
                    mma_bf16(a, Wh[kk], bh[sub], bh[sub + 2]);
                    mma_bf16(a, Wh[kk], bl[sub], bl[sub + 2]);
                    mma_bf16(a, Wl[kk], bh[sub], bh[sub + 2]);
                }
            }
        }
        __syncthreads();   // stage reads done before next prefetch overwrites
    }

    // ---- epilogue ----
    rsum0 += __shfl_xor_sync(0xffffffffu, rsum0, 1);
    rsum0 += __shfl_xor_sync(0xffffffffu, rsum0, 2);
    rsum1 += __shfl_xor_sync(0xffffffffu, rsum1, 1);
    rsum1 += __shfl_xor_sync(0xffffffffu, rsum1, 2);

    const float sink = tanhf(sink_sc[h]) + 1e-6f;
    const float al0  = __fdividef(1.f, rsum0 + sink + 1e-6f);
    const float al1  = __fdividef(1.f, rsum1 + sink + 1e-6f);

    #pragma unroll
    for (int j = 0; j < 8; j++) {
        int d0 = 8 * j + 2 * (lane & 3);
        float2 vn = *(const float2*)(v_nulls + h * 64 + d0);
        float2 o0, o1;
        o0.x = (acc[j][0] + sink * vn.x) * al0;
        o0.y = (acc[j][1] + sink * vn.y) * al0;
        o1.x = (acc[j][2] + sink * vn.x) * al1;
        o1.y = (acc[j][3] + sink * vn.y) * al1;
        *(float2*)(g_ctx + (size_t)r0g * (HTOT * DH) + h * 64 + d0) = o0;
        *(float2*)(g_ctx + (size_t)r1g * (HTOT * DH) + h * 64 + d0) = o1;
    }
}

// ---------------- average the 4 branches --------------------------------------
__global__ void avg_kernel()
{
    int idx = blockIdx.x * blockDim.x + threadIdx.x;
    if (idx >= T_SEQ * (DMODEL / 4)) return;
    int t   = idx >> 8;
    int c   = (idx & 255) << 2;
    int h16 = c >> 6;
    int d   = c & 63;
    float4 r = make_float4(0.f, 0.f, 0.f, 0.f);
    #pragma unroll
    for (int br = 0; br < 4; br++) {
        float4 v = *(const float4*)(g_ctx + (size_t)t * (HTOT * DH) +
                                    (br * 16 + h16) * DH + d);
        r.x += v.x; r.y += v.y; r.z += v.z; r.w += v.w;
    }
    r.x *= 0.25f; r.y *= 0.25f; r.z *= 0.25f; r.w *= 0.25f;
    *(float4*)(g_ctxavg + (size_t)t * DMODEL + c) = r;
}

// ---------------- launch -------------------------------------------------------
extern "C" void kernel_launch(void* const* d_in, const int* in_sizes, int n_in,
                              void* d_out, int out_size)
{
    const float* X     = (const float*)d_in[0];
    const float* Wq    = (const float*)d_in[1];
    const float* bq    = (const float*)d_in[2];
    const float* Wk    = (const float*)d_in[3];
    const float* bk    = (const float*)d_in[4];
    const float* Wv    = (const float*)d_in[5];
    const float* bv    = (const float*)d_in[6];
    const float* sink  = (const float*)d_in[7];
    const float* vnull = (const float*)d_in[8];
    const float* Wo    = (const float*)d_in[9];
    const float* bo    = (const float*)d_in[10];
    float* out         = (float*)d_out;

    float *QKV, *CA, *BQKV;
    cudaGetSymbolAddress((void**)&QKV,  g_QKV);
    cudaGetSymbolAddress((void**)&CA,   g_ctxavg);
    cudaGetSymbolAddress((void**)&BQKV, g_bqkv);
    __nv_bfloat16 *Xh, *Xl, *WqkvTh, *WqkvTl, *WoTh, *WoTl;
    cudaGetSymbolAddress((void**)&Xh,     g_Xh);
    cudaGetSymbolAddress((void**)&Xl,     g_Xl);
    cudaGetSymbolAddress((void**)&WqkvTh, g_WqkvTh);
    cudaGetSymbolAddress((void**)&WqkvTl, g_WqkvTl);
    cudaGetSymbolAddress((void**)&WoTh,   g_WoTh);
    cudaGetSymbolAddress((void**)&WoTl,   g_WoTl);

    const int gemm_smem = 2 * STG_B;                 // 65536
    cudaFuncSetAttribute(gemm_mma,
                         cudaFuncAttributeMaxDynamicSharedMemorySize, gemm_smem);
    const int attn_smem = 98304;                     // 32K Q + 2x32K stages
    cudaFuncSetAttribute(attn_mma_kernel,
                         cudaFuncAttributeMaxDynamicSharedMemorySize, attn_smem);

    bcat_kernel<<<(NQKV + 255) / 256, 256>>>(bq, bk, bv);
    esplit_kernel<<<T_SEQ * KDIM / 4 / 256, 256>>>(X, Xh, Xl, T_SEQ * KDIM);
    tsplit_qkv_kernel<<<dim3(NQKV / 32, KDIM / 32), 256>>>(Wq, Wk, Wv);

    // slot 3 (profiled): fused QKV projection
    gemm_mma<<<dim3(NQKV / 128, T_SEQ / 128), 256, gemm_smem>>>(
        Xh, Xl, WqkvTh, WqkvTl, BQKV, QKV, NQKV);

    tsplit_wo_kernel<<<dim3(DMODEL / 32, KDIM / 32), 256>>>(Wo);
    rope_table_kernel<<<(T_SEQ * 32 + 255) / 256, 256>>>();
    ropesplit_kernel<<<80 * T_SEQ * 32 / 256, 256>>>();
    vtsplit_kernel<<<dim3(HTOT * DH / 32, T_SEQ / 32), 256>>>();
    kscale_kernel<<<(NHEAD * T_SEQ * 32 + 255) / 256, 256>>>();

    attn_mma_kernel<<<dim3(8, HTOT), 256, attn_smem>>>(sink, vnull);

    avg_kernel<<<(T_SEQ * (DMODEL / 4) + 255) / 256, 256>>>();
    esplit_kernel<<<T_SEQ * KDIM / 4 / 256, 256>>>(CA, Xh, Xl, T_SEQ * KDIM);
    gemm_mma<<<dim3(DMODEL / 128, T_SEQ / 128), 256, gemm_smem>>>(
        Xh, Xl, WoTh, WoTl, bo, out, DMODEL);
}